// round 13
// baseline (speedup 1.0000x reference)
#include <cuda_runtime.h>
#include <cuda_bf16.h>
#include <cstdint>

#define B_    16
#define S_    10
#define D_    128
#define C_    256
#define NTOK  65536
#define NPB   4096
#define T_    20
#define CHUNK 128
#define NCHUNK 32
#define QSCALE 0.08838834764831845f

// ---- scratch ----
__device__ __nv_bfloat16 g_k[NTOK * D_];
__device__ __nv_bfloat16 g_v[NTOK * D_];
__device__ __nv_bfloat16 g_wkT[D_ * C_];
__device__ __nv_bfloat16 g_wvT[D_ * C_];
__device__ __nv_bfloat16 g_qb[B_ * 16 * D_];
__device__ float g_slots[B_ * S_ * D_];
__device__ float g_pnum[(size_t)B_ * NCHUNK * S_ * D_];
__device__ float g_pden[B_ * NCHUNK * S_];

__device__ __forceinline__ float2 warpRed2(float a, float b) {
    #pragma unroll
    for (int o = 16; o > 0; o >>= 1) {
        a += __shfl_xor_sync(0xffffffffu, a, o);
        b += __shfl_xor_sync(0xffffffffu, b, o);
    }
    return make_float2(a, b);
}
__device__ __forceinline__ float warpRed1(float a) {
    #pragma unroll
    for (int o = 16; o > 0; o >>= 1) a += __shfl_xor_sync(0xffffffffu, a, o);
    return a;
}

__device__ __forceinline__ uint32_t s2u(const void* p) {
    return (uint32_t)__cvta_generic_to_shared(p);
}
__device__ __forceinline__ float bf(const __nv_bfloat16 x) { return __bfloat162float(x); }

#define LDSM4(r, addr)                                                          \
    asm volatile("ldmatrix.sync.aligned.m8n8.x4.shared.b16 {%0,%1,%2,%3}, [%4];"\
                 : "=r"((r)[0]), "=r"((r)[1]), "=r"((r)[2]), "=r"((r)[3])       \
                 : "r"(addr))

#define LDSM4T(r, addr)                                                         \
    asm volatile("ldmatrix.sync.aligned.m8n8.x4.trans.shared.b16 {%0,%1,%2,%3}, [%4];"\
                 : "=r"((r)[0]), "=r"((r)[1]), "=r"((r)[2]), "=r"((r)[3])       \
                 : "r"(addr))

#define MMA_BF16(d, a, b0, b1)                                                  \
    asm volatile("mma.sync.aligned.m16n8k16.row.col.f32.bf16.bf16.f32 "         \
                 "{%0,%1,%2,%3}, {%4,%5,%6,%7}, {%8,%9}, {%0,%1,%2,%3};"        \
                 : "+f"((d)[0]), "+f"((d)[1]), "+f"((d)[2]), "+f"((d)[3])       \
                 : "r"((a)[0]), "r"((a)[1]), "r"((a)[2]), "r"((a)[3]),          \
                   "r"(b0), "r"(b1))

#define CPASYNC16(dst, src)                                                     \
    asm volatile("cp.async.cg.shared.global [%0], [%1], 16;"                    \
                 :: "r"(dst), "l"(src) : "memory")
#define CPCOMMIT() asm volatile("cp.async.commit_group;" ::: "memory")
#define CPWAIT(n)  asm volatile("cp.async.wait_group %0;" :: "n"(n) : "memory")

// ============================================================================
// Kernel 0a/0b: weight transpose + bf16 convert
// ============================================================================
__global__ void k_prepk(const float* __restrict__ Wk)
{
    int d = blockIdx.x, c = threadIdx.x;
    g_wkT[d * C_ + c] = __float2bfloat16(Wk[c * D_ + d]);
}
__global__ void k_prepv(const float* __restrict__ Wv)
{
    int d = blockIdx.x, c = threadIdx.x;
    g_wvT[d * C_ + c] = __float2bfloat16(Wv[c * D_ + d]);
}

// ============================================================================
// Kernel 1: fused LN + K,V projection, warp-specialized, BATCHED producer
// loads (16 LDG.128 in flight per warp -> ~5 TB/s obs streaming).
// ============================================================================
#define XSTRIDE 264
#define SMEM1 (3 * 128 * XSTRIDE * 2)
__global__ __launch_bounds__(512, 1) void k_ln_kv(
    const float* __restrict__ obs, const float* __restrict__ niw,
    const float* __restrict__ nib)
{
    extern __shared__ char smx[];
    __nv_bfloat16* ha0 = (__nv_bfloat16*)smx;           // [64][264]
    __nv_bfloat16* ha1 = ha0 + 64 * XSTRIDE;
    __nv_bfloat16* wks = ha1 + 64 * XSTRIDE;            // [128][264]
    __nv_bfloat16* wvs = wks + 128 * XSTRIDE;

    const int tid  = threadIdx.x;
    const int wid  = tid >> 5;
    const int lane = tid & 31;
    const int tblk = blockIdx.x * 512;

    {
        const uint4* gk4 = (const uint4*)g_wkT;
        const uint4* gv4 = (const uint4*)g_wvT;
        #pragma unroll
        for (int i = 0; i < 8; i++) {
            int u = tid + i * 512;
            int row = u >> 5, c = u & 31;
            *(uint4*)((char*)wks + row * (XSTRIDE * 2) + c * 16) = gk4[u];
            *(uint4*)((char*)wvs + row * (XSTRIDE * 2) + c * 16) = gv4[u];
        }
    }

    if (wid >= 8) {
        // ================= PRODUCER: LayerNorm (batched loads) =============
        const int p  = wid - 8;
        const int c0 = lane * 4;
        float4 nw0 = *(const float4*)(niw + c0);
        float4 nw1 = *(const float4*)(niw + c0 + 128);
        float4 nb0 = *(const float4*)(nib + c0);
        float4 nb1 = *(const float4*)(nib + c0 + 128);

        #pragma unroll 1
        for (int h = -1; h < 8; h++) {
            if (h < 7) {
                const int hh = h + 1;
                __nv_bfloat16* buf = (hh & 1) ? ha1 : ha0;
                const int t0 = tblk + hh * 64;
                // batch ALL loads first: 16 LDG.128 in flight
                float4 v0[8], v1[8];
                #pragma unroll
                for (int i = 0; i < 8; i++) {
                    const float4* src =
                        (const float4*)(obs + (size_t)(t0 + p * 8 + i) * C_);
                    v0[i] = __ldcs(src + lane);
                    v1[i] = __ldcs(src + lane + 32);
                }
                #pragma unroll
                for (int i = 0; i < 8; i++) {
                    int r = p * 8 + i;
                    float s  = v0[i].x + v0[i].y + v0[i].z + v0[i].w
                             + v1[i].x + v1[i].y + v1[i].z + v1[i].w;
                    float ss = v0[i].x*v0[i].x + v0[i].y*v0[i].y
                             + v0[i].z*v0[i].z + v0[i].w*v0[i].w
                             + v1[i].x*v1[i].x + v1[i].y*v1[i].y
                             + v1[i].z*v1[i].z + v1[i].w*v1[i].w;
                    float2 red = warpRed2(s, ss);
                    float mu  = red.x * (1.0f / 256.0f);
                    float var = red.y * (1.0f / 256.0f) - mu * mu;
                    float rsg = rsqrtf(var + 1e-5f);
                    char* xr = (char*)buf + r * (XSTRIDE * 2);
                    *(__nv_bfloat162*)(xr + (c0 + 0) * 2) =
                        __floats2bfloat162_rn((v0[i].x - mu) * rsg * nw0.x + nb0.x,
                                              (v0[i].y - mu) * rsg * nw0.y + nb0.y);
                    *(__nv_bfloat162*)(xr + (c0 + 2) * 2) =
                        __floats2bfloat162_rn((v0[i].z - mu) * rsg * nw0.z + nb0.z,
                                              (v0[i].w - mu) * rsg * nw0.w + nb0.w);
                    *(__nv_bfloat162*)(xr + (c0 + 128) * 2) =
                        __floats2bfloat162_rn((v1[i].x - mu) * rsg * nw1.x + nb1.x,
                                              (v1[i].y - mu) * rsg * nw1.y + nb1.y);
                    *(__nv_bfloat162*)(xr + (c0 + 130) * 2) =
                        __floats2bfloat162_rn((v1[i].z - mu) * rsg * nw1.z + nb1.z,
                                              (v1[i].w - mu) * rsg * nw1.w + nb1.w);
                }
            }
            __syncthreads();
        }
    } else {
        // ================= CONSUMER: MMA + epilogue ========================
        const int mat = wid >> 2;
        const int wm  = wid & 1;
        const int wn  = (wid >> 1) & 1;
        const __nv_bfloat16* wsm = mat ? wvs : wks;
        const int ga = lane >> 3, ra = lane & 7;
        const uint32_t aB0 = s2u(wsm) +
            (uint32_t)(((wn * 64 + ra + ((ga >> 1) << 3)) * XSTRIDE + ((ga & 1) << 3)) * 2);
        const uint32_t aAoff =
            (uint32_t)(((wm * 32 + ra + ((ga & 1) << 3)) * XSTRIDE + ((ga >> 1) << 3)) * 2);
        const int qrow = lane >> 2;
        const int qcol = (lane & 3) * 2;
        __nv_bfloat16* gout = mat ? g_v : g_k;

        __syncthreads();
        #pragma unroll 1
        for (int h = 0; h < 8; h++) {
            const __nv_bfloat16* abuf = (h & 1) ? ha1 : ha0;
            uint32_t aA = s2u(abuf) + aAoff;
            uint32_t aB = aB0;

            float acc[2][8][4];
            #pragma unroll
            for (int mi = 0; mi < 2; mi++)
                #pragma unroll
                for (int nj = 0; nj < 8; nj++)
                    #pragma unroll
                    for (int e = 0; e < 4; e++) acc[mi][nj][e] = 0.f;

            #pragma unroll 1
            for (int s = 0; s < 16; s++) {
                uint32_t A0[4], A1[4], Bx[4][4];
                LDSM4(A0, aA);
                LDSM4(A1, aA + 16 * (XSTRIDE * 2));
                #pragma unroll
                for (int j = 0; j < 4; j++)
                    LDSM4(Bx[j], aB + j * 16 * (XSTRIDE * 2));
                #pragma unroll
                for (int nj = 0; nj < 8; nj++) {
                    uint32_t b0 = Bx[nj >> 1][(nj & 1) * 2];
                    uint32_t b1 = Bx[nj >> 1][(nj & 1) * 2 + 1];
                    MMA_BF16(acc[0][nj], A0, b0, b1);
                    MMA_BF16(acc[1][nj], A1, b0, b1);
                }
                aA += 32;
                aB += 32;
            }

            const int rbase = tblk + h * 64 + wm * 32;
            #pragma unroll
            for (int mi = 0; mi < 2; mi++) {
                #pragma unroll
                for (int nj = 0; nj < 8; nj++) {
                    int c  = wn * 64 + nj * 8 + qcol;
                    int r0 = rbase + mi * 16 + qrow;
                    *(__nv_bfloat162*)(gout + (size_t)r0 * D_ + c) =
                        __floats2bfloat162_rn(acc[mi][nj][0], acc[mi][nj][1]);
                    *(__nv_bfloat162*)(gout + (size_t)(r0 + 8) * D_ + c) =
                        __floats2bfloat162_rn(acc[mi][nj][2], acc[mi][nj][3]);
                }
            }
            __syncthreads();
        }
    }
}

// ============================================================================
// LN stats helper (256-thread block, 128 live values in threads 0-127)
// ============================================================================
__device__ __forceinline__ void ln_stats(float x, float* r1, float* r2,
                                         float& mu, float& rs) {
    float2 red = warpRed2(x, x * x);
    int wid = threadIdx.x >> 5, lane = threadIdx.x & 31;
    if (lane == 0) { r1[wid] = red.x; r2[wid] = red.y; }
    __syncthreads();
    float Sm = 0.f, Sq = 0.f;
    #pragma unroll
    for (int i = 0; i < 8; i++) { Sm += r1[i]; Sq += r2[i]; }
    mu = Sm * (1.0f / 128.0f);
    float var = Sq * (1.0f / 128.0f) - mu * mu;
    rs = rsqrtf(var + 1e-5f);
}

// pair-wise LN stats: threads 0-127 pair0, 128-255 pair1
__device__ __forceinline__ void ln_stats2(float x, float* r1, float* r2,
                                          int pr, float& mu, float& rs) {
    float2 red = warpRed2(x, x * x);
    int wid = threadIdx.x >> 5, lane = threadIdx.x & 31;
    if (lane == 0) { r1[wid] = red.x; r2[wid] = red.y; }
    __syncthreads();
    float Sm = 0.f, Sq = 0.f;
    #pragma unroll
    for (int i = 0; i < 4; i++) { Sm += r1[pr * 4 + i]; Sq += r2[pr * 4 + i]; }
    mu = Sm * (1.0f / 128.0f);
    float var = Sq * (1.0f / 128.0f) - mu * mu;
    rs = rsqrtf(var + 1e-5f);
}

// ============================================================================
// Kernel 2: slot init + q-pad zero + LN + q projection (fused). grid 160.
// ============================================================================
__global__ void k_sq_init(const float* __restrict__ noise, const float* __restrict__ smu,
                          const float* __restrict__ sls, const float* __restrict__ nsw,
                          const float* __restrict__ nsb, const float* __restrict__ Wq)
{
    __shared__ float sl[128];
    __shared__ float hm[128];
    __shared__ float hid[256];
    __shared__ float r1[8], r2[8];
    const int tid = threadIdx.x;
    const int b = blockIdx.x / 10;
    const int s = blockIdx.x % 10;

    if (tid < 128) {
        float v = smu[tid] + expf(sls[tid]) * noise[blockIdx.x * 128 + tid];
        g_slots[blockIdx.x * 128 + tid] = v;
        sl[tid] = v;
        if (s < 6)
            g_qb[b * 2048 + (10 + s) * 128 + tid] = __float2bfloat16(0.f);
    }
    __syncthreads();

    float x = (tid < 128) ? sl[tid] : 0.f;
    float mu, rs;
    ln_stats(x, r1, r2, mu, rs);
    if (tid < 128) hm[tid] = (x - mu) * rs * nsw[tid] + nsb[tid];
    __syncthreads();
    {
        int d = tid & 127, half = tid >> 7;
        const float* wq = Wq + half * 64 * 128;
        const float* hh = hm + half * 64;
        float a0 = 0, a1 = 0, a2 = 0, a3 = 0;
        #pragma unroll
        for (int c = 0; c < 64; c += 4) {
            a0 += hh[c + 0] * wq[(c + 0) * 128 + d];
            a1 += hh[c + 1] * wq[(c + 1) * 128 + d];
            a2 += hh[c + 2] * wq[(c + 2) * 128 + d];
            a3 += hh[c + 3] * wq[(c + 3) * 128 + d];
        }
        hid[tid] = (a0 + a1) + (a2 + a3);
    }
    __syncthreads();
    if (tid < 128)
        g_qb[b * 2048 + s * 128 + tid] =
            __float2bfloat16((hid[tid] + hid[tid + 128]) * QSCALE);
}

// ============================================================================
// Kernel 3: fused attention chunk (unchanged from 126us best).
// ============================================================================
#define TS 136
#define LSTR 132
#define ATT_SMEM (2*128*TS*2 + 16*TS*2 + 16*TS*2 + 16*LSTR*4)
__global__ __launch_bounds__(256, 2) void k_attn()
{
    extern __shared__ char sm2[];
    __nv_bfloat16* tileK = (__nv_bfloat16*)sm2;
    __nv_bfloat16* tileV = tileK + 128 * TS;
    __nv_bfloat16* Qs    = tileV + 128 * TS;
    __nv_bfloat16* aBm   = Qs + 16 * TS;
    float* Ls            = (float*)(aBm + 16 * TS);

    const int tid  = threadIdx.x;
    const int w    = tid >> 5;
    const int lane = tid & 31;
    const int ck   = blockIdx.x;
    const int b    = blockIdx.y;

    {
        const uint4* srcK = (const uint4*)(g_k + ((size_t)b * NPB + ck * CHUNK) * D_);
        const uint4* srcV = (const uint4*)(g_v + ((size_t)b * NPB + ck * CHUNK) * D_);
        const uint32_t dK = s2u(tileK), dV = s2u(tileV);
        #pragma unroll
        for (int i = 0; i < 8; i++) {
            int u = tid + i * 256;
            int row = u >> 4, c = u & 15;
            CPASYNC16(dK + row * (TS * 2) + c * 16, srcK + u);
        }
        CPCOMMIT();
        #pragma unroll
        for (int i = 0; i < 8; i++) {
            int u = tid + i * 256;
            int row = u >> 4, c = u & 15;
            CPASYNC16(dV + row * (TS * 2) + c * 16, srcV + u);
        }
        CPCOMMIT();
    }

    {
        int row = tid >> 4, c = tid & 15;
        *(uint4*)((char*)Qs + row * (TS * 2) + c * 16) =
            ((const uint4*)(g_qb + b * 2048))[tid];
    }
    if (tid < 102) {
        *(uint4*)((char*)aBm + 10 * (TS * 2) + tid * 16) = make_uint4(0, 0, 0, 0);
    }

    CPWAIT(1);
    __syncthreads();

    const int ga = lane >> 3, ra = lane & 7;
    const int qrow = lane >> 2, qcol = (lane & 3) * 2;
    const uint32_t baseA_q = s2u(Qs) +
        (uint32_t)(((ra + ((ga & 1) << 3)) * TS + ((ga >> 1) << 3)) * 2);
    const uint32_t baseB_k = s2u(tileK) +
        (uint32_t)(((w * 16 + ra + ((ga >> 1) << 3)) * TS + ((ga & 1) << 3)) * 2);

    {
        float lacc[2][4] = {{0,0,0,0},{0,0,0,0}};
        #pragma unroll
        for (int ks = 0; ks < 8; ks++) {
            uint32_t A[4], Bx[4];
            LDSM4(A, baseA_q + ks * 32);
            LDSM4(Bx, baseB_k + ks * 32);
            MMA_BF16(lacc[0], A, Bx[0], Bx[1]);
            MMA_BF16(lacc[1], A, Bx[2], Bx[3]);
        }
        #pragma unroll
        for (int nj = 0; nj < 2; nj++) {
            int t = w * 16 + nj * 8 + qcol;
            Ls[qrow * LSTR + t]           = lacc[nj][0];
            Ls[qrow * LSTR + t + 1]       = lacc[nj][1];
            Ls[(qrow + 8) * LSTR + t]     = lacc[nj][2];
            Ls[(qrow + 8) * LSTR + t + 1] = lacc[nj][3];
        }
    }
    __syncthreads();

    if (tid < 128) {
        float v[10]; float m = -1e30f;
        #pragma unroll
        for (int s = 0; s < 10; s++) { v[s] = Ls[s * LSTR + tid]; m = fmaxf(m, v[s]); }
        float sum = 0.f;
        #pragma unroll
        for (int s = 0; s < 10; s++) { v[s] = __expf(v[s] - m); sum += v[s]; }
        float inv = 1.0f / sum;
        #pragma unroll
        for (int s = 0; s < 10; s++) aBm[s * TS + tid] = __float2bfloat16(v[s] * inv);
    }
    __syncthreads();

    for (int s = w; s < 10; s += 8) {
        float p = bf(aBm[s * TS + lane]) + bf(aBm[s * TS + lane + 32])
                + bf(aBm[s * TS + lane + 64]) + bf(aBm[s * TS + lane + 96]);
        p = warpRed1(p);
        if (lane == 0) g_pden[(b * NCHUNK + ck) * S_ + s] = p;
    }

    CPWAIT(0);
    __syncthreads();

    {
        const uint32_t baseA_a = s2u(aBm) +
            (uint32_t)(((ra + ((ga & 1) << 3)) * TS + ((ga >> 1) << 3)) * 2);
        const uint32_t baseB_v = s2u(tileV) +
            (uint32_t)(((((ga & 1) << 3) + ra) * TS + w * 16 + ((ga >> 1) << 3)) * 2);
        float nacc[2][4] = {{0,0,0,0},{0,0,0,0}};
        #pragma unroll
        for (int ks = 0; ks < 8; ks++) {
            uint32_t A[4], Bt[4];
            LDSM4(A, baseA_a + ks * 32);
            LDSM4T(Bt, baseB_v + ks * (16 * TS * 2));
            MMA_BF16(nacc[0], A, Bt[0], Bt[1]);
            MMA_BF16(nacc[1], A, Bt[2], Bt[3]);
        }
        float* dst = g_pnum + (size_t)(b * NCHUNK + ck) * S_ * D_;
        #pragma unroll
        for (int nj = 0; nj < 2; nj++) {
            int d = w * 16 + nj * 8 + qcol;
            *(float2*)(dst + qrow * D_ + d) = make_float2(nacc[nj][0], nacc[nj][1]);
            if (qrow + 8 < 10)
                *(float2*)(dst + (qrow + 8) * D_ + d) = make_float2(nacc[nj][2], nacc[nj][3]);
        }
    }
}

// ============================================================================
// Kernel 4: slot update + q projection, 2 pairs/block, grid 80.
// Each weight load feeds 2 FMAs -> halves redundant L2 weight traffic.
// ============================================================================
__global__ void k_slotq(const float* __restrict__ nmw, const float* __restrict__ nmb,
                        const float* __restrict__ w1, const float* __restrict__ b1,
                        const float* __restrict__ w2, const float* __restrict__ b2,
                        const float* __restrict__ nsw, const float* __restrict__ nsb,
                        const float* __restrict__ Wq)
{
    __shared__ float sl[2][128];
    __shared__ float hm[2][128];
    __shared__ float hid[2][256];
    __shared__ float prt[2][128];
    __shared__ float r1[8], r2[8];
    __shared__ float sdn[2];
    const int tid = threadIdx.x;
    const int wid = tid >> 5;
    const int lane = tid & 31;
    const int p0 = blockIdx.x * 2;
    const int pr = tid >> 7;          // pair this thread owns
    const int d  = tid & 127;

    // denominators: warps 0,1 -> pairs 0,1
    if (wid < 2) {
        int p = p0 + wid, b = p / 10, s = p % 10;
        float v = g_pden[(b * NCHUNK + lane) * S_ + s];
        v = warpRed1(v);
        if (lane == 0) sdn[wid] = v;
    }
    // numerator reduce: thread (pr, d)
    {
        int p = p0 + pr, b = p / 10, s = p % 10;
        const float* src = g_pnum + ((size_t)(b * NCHUNK) * S_ + s) * D_ + d;
        float u0 = 0, u1 = 0, u2 = 0, u3 = 0;
        #pragma unroll
        for (int ch = 0; ch < NCHUNK; ch += 4) {
            u0 += __ldcs(src + (size_t)(ch + 0) * S_ * D_);
            u1 += __ldcs(src + (size_t)(ch + 1) * S_ * D_);
            u2 += __ldcs(src + (size_t)(ch + 2) * S_ * D_);
            u3 += __ldcs(src + (size_t)(ch + 3) * S_ * D_);
        }
        sl[pr][d] = (u0 + u1) + (u2 + u3);
    }
    __syncthreads();
    float slot_new = g_slots[(p0 + pr) * D_ + d] + sl[pr][d] / (sdn[pr] + 1e-8f);
    {
        float mu, rs;
        ln_stats2(slot_new, r1, r2, pr, mu, rs);
        hm[pr][d] = (slot_new - mu) * rs * nmw[d] + nmb[d];
        sl[pr][d] = slot_new;
    }
    __syncthreads();
    // MLP1: thread = column tid, both pairs per weight load
    {
        float a0 = b1[tid], a1 = a0;
        #pragma unroll 8
        for (int c = 0; c < 128; c++) {
            float wv = w1[c * 256 + tid];
            a0 += hm[0][c] * wv;
            a1 += hm[1][c] * wv;
        }
        hid[0][tid] = fmaxf(a0, 0.f);
        hid[1][tid] = fmaxf(a1, 0.f);
    }
    __syncthreads();
    // MLP2: threads 0-127, both pairs per weight load
    if (tid < 128) {
        float o0 = 0, o1 = 0, o2 = 0, o3 = 0;
        #pragma unroll 8
        for (int j = 0; j < 256; j += 2) {
            float wa = w2[j * 128 + tid];
            float wb = w2[(j + 1) * 128 + tid];
            o0 += hid[0][j] * wa;  o2 += hid[0][j + 1] * wb;
            o1 += hid[1][j] * wa;  o3 += hid[1][j + 1] * wb;
        }
        float bb = b2[tid];
        float sf0 = sl[0][tid] + bb + o0 + o2;
        float sf1 = sl[1][tid] + bb + o1 + o3;
        sl[0][tid] = sf0;
        sl[1][tid] = sf1;
        g_slots[(p0 + 0) * D_ + tid] = sf0;
        g_slots[(p0 + 1) * D_ + tid] = sf1;
    }
    __syncthreads();

    // LN(ns) + q projection (split-k halves x both pairs)
    {
        float x = sl[pr][d];
        float mu, rs;
        ln_stats2(x, r1, r2, pr, mu, rs);
        hm[pr][d] = (x - mu) * rs * nsw[d] + nsb[d];
    }
    __syncthreads();
    {
        int half = tid >> 7;
        const float* wq = Wq + half * 64 * 128;
        float q0 = 0, q1 = 0;
        #pragma unroll 8
        for (int ci = 0; ci < 64; ci++) {
            float wv = wq[ci * 128 + d];
            q0 += hm[0][half * 64 + ci] * wv;
            q1 += hm[1][half * 64 + ci] * wv;
        }
        if (half == 1) { prt[0][d] = q0; prt[1][d] = q1; }
        __syncthreads();
        if (half == 0) {
            int p0a = p0, b0a = p0a / 10, s0a = p0a % 10;
            int p1a = p0 + 1, b1a = p1a / 10, s1a = p1a % 10;
            g_qb[b0a * 2048 + s0a * 128 + d] =
                __float2bfloat16((q0 + prt[0][d]) * QSCALE);
            g_qb[b1a * 2048 + s1a * 128 + d] =
                __float2bfloat16((q1 + prt[1][d]) * QSCALE);
        }
    }
}

// ============================================================================
// Kernel 5: final update + heads, 2 pairs/block, grid 80.
// ============================================================================
__global__ void k_last(const float* __restrict__ nmw, const float* __restrict__ nmb,
                       const float* __restrict__ w1, const float* __restrict__ b1,
                       const float* __restrict__ w2, const float* __restrict__ b2,
                       const float* __restrict__ pw1, const float* __restrict__ pb1,
                       const float* __restrict__ pw2, const float* __restrict__ pb2,
                       const float* __restrict__ tw, const float* __restrict__ tb,
                       float* __restrict__ out)
{
    __shared__ float sl[2][128];
    __shared__ float hm[2][128];
    __shared__ float hid[2][256];
    __shared__ float r1[8], r2[8];
    __shared__ float sdn[2];
    const int tid = threadIdx.x;
    const int wid = tid >> 5;
    const int lane = tid & 31;
    const int p0 = blockIdx.x * 2;
    const int pr = tid >> 7;
    const int d  = tid & 127;

    if (wid < 2) {
        int p = p0 + wid, b = p / 10, s = p % 10;
        float v = g_pden[(b * NCHUNK + lane) * S_ + s];
        v = warpRed1(v);
        if (lane == 0) sdn[wid] = v;
    }
    {
        int p = p0 + pr, b = p / 10, s = p % 10;
        const float* src = g_pnum + ((size_t)(b * NCHUNK) * S_ + s) * D_ + d;
        float u0 = 0, u1 = 0, u2 = 0, u3 = 0;
        #pragma unroll
        for (int ch = 0; ch < NCHUNK; ch += 4) {
            u0 += __ldcs(src + (size_t)(ch + 0) * S_ * D_);
            u1 += __ldcs(src + (size_t)(ch + 1) * S_ * D_);
            u2 += __ldcs(src + (size_t)(ch + 2) * S_ * D_);
            u3 += __ldcs(src + (size_t)(ch + 3) * S_ * D_);
        }
        sl[pr][d] = (u0 + u1) + (u2 + u3);
    }
    __syncthreads();
    float slot_new = g_slots[(p0 + pr) * D_ + d] + sl[pr][d] / (sdn[pr] + 1e-8f);
    {
        float mu, rs;
        ln_stats2(slot_new, r1, r2, pr, mu, rs);
        hm[pr][d] = (slot_new - mu) * rs * nmw[d] + nmb[d];
        sl[pr][d] = slot_new;
    }
    __syncthreads();
    {
        float a0 = b1[tid], a1 = a0;
        #pragma unroll 8
        for (int c = 0; c < 128; c++) {
            float wv = w1[c * 256 + tid];
            a0 += hm[0][c] * wv;
            a1 += hm[1][c] * wv;
        }
        hid[0][tid] = fmaxf(a0, 0.f);
        hid[1][tid] = fmaxf(a1, 0.f);
    }
    __syncthreads();
    if (tid < 128) {
        float o0 = 0, o1 = 0, o2 = 0, o3 = 0;
        #pragma unroll 8
        for (int j = 0; j < 256; j += 2) {
            float wa = w2[j * 128 + tid];
            float wb = w2[(j + 1) * 128 + tid];
            o0 += hid[0][j] * wa;  o2 += hid[0][j + 1] * wb;
            o1 += hid[1][j] * wa;  o3 += hid[1][j + 1] * wb;
        }
        float bb = b2[tid];
        sl[0][tid] = sl[0][tid] + bb + o0 + o2;
        sl[1][tid] = sl[1][tid] + bb + o1 + o3;
    }
    __syncthreads();

    // heads: objects
    {
        float a0 = pb1[tid], a1 = a0;
        #pragma unroll 8
        for (int c = 0; c < 128; c++) {
            float wv = pw1[c * 256 + tid];
            a0 += sl[0][c] * wv;
            a1 += sl[1][c] * wv;
        }
        hid[0][tid] = fmaxf(a0, 0.f);
        hid[1][tid] = fmaxf(a1, 0.f);
    }
    __syncthreads();
    if (tid < 128) {
        float o0 = 0, o1 = 0, o2 = 0, o3 = 0;
        #pragma unroll 8
        for (int j = 0; j < 256; j += 2) {
            float wa = pw2[j * 128 + tid];
            float wb = pw2[(j + 1) * 128 + tid];
            o0 += hid[0][j] * wa;  o2 += hid[0][j + 1] * wb;
            o1 += hid[1][j] * wa;  o3 += hid[1][j + 1] * wb;
        }
        float bb = pb2[tid];
        out[(p0 + 0) * 128 + tid] = bb + o0 + o2;
        out[(p0 + 1) * 128 + tid] = bb + o1 + o3;
    }
    // types head: 2 pairs x 20 types
    if (tid < 2 * T_) {
        int pp = tid / T_, tt = tid % T_;
        float o = tb[tt];
        #pragma unroll 8
        for (int c = 0; c < 128; c++) o += sl[pp][c] * tw[c * T_ + tt];
        out[B_ * S_ * D_ + (p0 + pp) * T_ + tt] = o;
    }
}

// ============================================================================
extern "C" void kernel_launch(void* const* d_in, const int* in_sizes, int n_in,
                              void* d_out, int out_size)
{
    const float* obs  = (const float*)d_in[0];
    const float* noise= (const float*)d_in[1];
    const float* smu  = (const float*)d_in[2];
    const float* sls  = (const float*)d_in[3];
    const float* niw  = (const float*)d_in[4];
    const float* nib  = (const float*)d_in[5];
    const float* nsw  = (const float*)d_in[6];
    const float* nsb  = (const float*)d_in[7];
    const float* nmw  = (const float*)d_in[8];
    const float* nmb  = (const float*)d_in[9];
    const float* Wq   = (const float*)d_in[10];
    const float* Wk   = (const float*)d_in[11];
    const float* Wv   = (const float*)d_in[12];
    const float* mw1  = (const float*)d_in[13];
    const float* mb1  = (const float*)d_in[14];
    const float* mw2  = (const float*)d_in[15];
    const float* mb2  = (const float*)d_in[16];
    const float* pw1  = (const float*)d_in[17];
    const float* pb1  = (const float*)d_in[18];
    const float* pw2  = (const float*)d_in[19];
    const float* pb2  = (const float*)d_in[20];
    const float* tcw  = (const float*)d_in[21];
    const float* tcb  = (const float*)d_in[22];
    float* out = (float*)d_out;

    cudaFuncSetAttribute(k_ln_kv, cudaFuncAttributeMaxDynamicSharedMemorySize, SMEM1);
    cudaFuncSetAttribute(k_attn,  cudaFuncAttributeMaxDynamicSharedMemorySize, ATT_SMEM);

    // launch order: ncu capture (4th launch) lands on k_ln_kv
    k_prepk<<<D_, C_>>>(Wk);                                             // 1
    k_prepv<<<D_, C_>>>(Wv);                                             // 2
    k_sq_init<<<160, 256>>>(noise, smu, sls, nsw, nsb, Wq);              // 3
    k_ln_kv<<<NTOK / 512, 512, SMEM1>>>(obs, niw, nib);                  // 4 <- ncu
    dim3 g2(NCHUNK, B_);
    for (int it = 0; it < 3; it++) {
        k_attn<<<g2, 256, ATT_SMEM>>>();
        if (it < 2)
            k_slotq<<<80, 256>>>(nmw, nmb, mw1, mb1, mw2, mb2, nsw, nsb, Wq);
        else
            k_last<<<80, 256>>>(nmw, nmb, mw1, mb1, mw2, mb2,
                                pw1, pb1, pw2, pb2, tcw, tcb, out);
    }
}

// round 14
// speedup vs baseline: 1.1730x; 1.1730x over previous
#include <cuda_runtime.h>
#include <cuda_bf16.h>
#include <cstdint>

#define B_    16
#define S_    10
#define D_    128
#define C_    256
#define NTOK  65536
#define NPB   4096
#define T_    20
#define CHUNK 128
#define NCHUNK 32
#define QSCALE 0.08838834764831845f

// ---- scratch ----
__device__ __nv_bfloat16 g_k[NTOK * D_];
__device__ __nv_bfloat16 g_v[NTOK * D_];
__device__ __nv_bfloat16 g_wkT[D_ * C_];
__device__ __nv_bfloat16 g_wvT[D_ * C_];
__device__ __nv_bfloat16 g_qb[B_ * 16 * D_];
__device__ float g_slots[B_ * S_ * D_];
__device__ float g_pnum[(size_t)B_ * NCHUNK * S_ * D_];
__device__ float g_pden[B_ * NCHUNK * S_];

__device__ __forceinline__ float2 warpRed2(float a, float b) {
    #pragma unroll
    for (int o = 16; o > 0; o >>= 1) {
        a += __shfl_xor_sync(0xffffffffu, a, o);
        b += __shfl_xor_sync(0xffffffffu, b, o);
    }
    return make_float2(a, b);
}
__device__ __forceinline__ float warpRed1(float a) {
    #pragma unroll
    for (int o = 16; o > 0; o >>= 1) a += __shfl_xor_sync(0xffffffffu, a, o);
    return a;
}

__device__ __forceinline__ uint32_t s2u(const void* p) {
    return (uint32_t)__cvta_generic_to_shared(p);
}
__device__ __forceinline__ float bf(const __nv_bfloat16 x) { return __bfloat162float(x); }

#define LDSM4(r, addr)                                                          \
    asm volatile("ldmatrix.sync.aligned.m8n8.x4.shared.b16 {%0,%1,%2,%3}, [%4];"\
                 : "=r"((r)[0]), "=r"((r)[1]), "=r"((r)[2]), "=r"((r)[3])       \
                 : "r"(addr))

#define LDSM4T(r, addr)                                                         \
    asm volatile("ldmatrix.sync.aligned.m8n8.x4.trans.shared.b16 {%0,%1,%2,%3}, [%4];"\
                 : "=r"((r)[0]), "=r"((r)[1]), "=r"((r)[2]), "=r"((r)[3])       \
                 : "r"(addr))

#define MMA_BF16(d, a, b0, b1)                                                  \
    asm volatile("mma.sync.aligned.m16n8k16.row.col.f32.bf16.bf16.f32 "         \
                 "{%0,%1,%2,%3}, {%4,%5,%6,%7}, {%8,%9}, {%0,%1,%2,%3};"        \
                 : "+f"((d)[0]), "+f"((d)[1]), "+f"((d)[2]), "+f"((d)[3])       \
                 : "r"((a)[0]), "r"((a)[1]), "r"((a)[2]), "r"((a)[3]),          \
                   "r"(b0), "r"(b1))

#define CPASYNC16(dst, src)                                                     \
    asm volatile("cp.async.cg.shared.global [%0], [%1], 16;"                    \
                 :: "r"(dst), "l"(src) : "memory")
#define CPCOMMIT() asm volatile("cp.async.commit_group;" ::: "memory")
#define CPWAIT(n)  asm volatile("cp.async.wait_group %0;" :: "n"(n) : "memory")

// ============================================================================
// Kernel 0a/0b: weight transpose + bf16 convert
// ============================================================================
__global__ void k_prepk(const float* __restrict__ Wk)
{
    int d = blockIdx.x, c = threadIdx.x;
    g_wkT[d * C_ + c] = __float2bfloat16(Wk[c * D_ + d]);
}
__global__ void k_prepv(const float* __restrict__ Wv)
{
    int d = blockIdx.x, c = threadIdx.x;
    g_wvT[d * C_ + c] = __float2bfloat16(Wv[c * D_ + d]);
}

// ============================================================================
// Kernel 1: fused LN + K,V projection. NON-specialized, batch-4 loads:
// all 16 warps load (8 LDG.128 in flight each -> ~6 TB/s), LN, then all
// 16 warps MMA one m32 x n32 tile (8 tiles K + 8 tiles V per 64-tok half).
// LN batch registers and MMA accumulators have disjoint liveness.
// ============================================================================
#define XSTRIDE 264
#define SMEM1 ((64 + 2 * 128) * XSTRIDE * 2)
__global__ __launch_bounds__(512, 1) void k_ln_kv(
    const float* __restrict__ obs, const float* __restrict__ niw,
    const float* __restrict__ nib)
{
    extern __shared__ char smx[];
    __nv_bfloat16* ha  = (__nv_bfloat16*)smx;           // [64][264]
    __nv_bfloat16* wks = ha + 64 * XSTRIDE;             // [128][264]
    __nv_bfloat16* wvs = wks + 128 * XSTRIDE;

    const int tid  = threadIdx.x;
    const int wid  = tid >> 5;
    const int lane = tid & 31;
    const int tblk = blockIdx.x * 512;

    // stage bf16 transposed weights once per block
    {
        const uint4* gk4 = (const uint4*)g_wkT;
        const uint4* gv4 = (const uint4*)g_wvT;
        #pragma unroll
        for (int i = 0; i < 8; i++) {
            int u = tid + i * 512;
            int row = u >> 5, c = u & 31;
            *(uint4*)((char*)wks + row * (XSTRIDE * 2) + c * 16) = gk4[u];
            *(uint4*)((char*)wvs + row * (XSTRIDE * 2) + c * 16) = gv4[u];
        }
    }

    // LN params (per lane)
    const int c0 = lane * 4;
    float4 nw0 = *(const float4*)(niw + c0);
    float4 nw1 = *(const float4*)(niw + c0 + 128);
    float4 nb0 = *(const float4*)(nib + c0);
    float4 nb1 = *(const float4*)(nib + c0 + 128);

    // MMA tile assignment: mat = K/V, wm2 = m32 block, wn4 = n32 block
    const int mat = wid >> 3;
    const int wm2 = wid & 1;
    const int wn4 = (wid >> 1) & 3;
    const __nv_bfloat16* wsm = mat ? wvs : wks;
    const int ga = lane >> 3, ra = lane & 7;
    const uint32_t aAoff =
        (uint32_t)(((wm2 * 32 + ra + ((ga & 1) << 3)) * XSTRIDE + ((ga >> 1) << 3)) * 2);
    const uint32_t aB0 = s2u(wsm) +
        (uint32_t)(((wn4 * 32 + ra + ((ga >> 1) << 3)) * XSTRIDE + ((ga & 1) << 3)) * 2);
    const int qrow = lane >> 2;
    const int qcol = (lane & 3) * 2;
    __nv_bfloat16* gout = mat ? g_v : g_k;

    __syncthreads();

    #pragma unroll 1
    for (int h = 0; h < 8; h++) {
        const int t0 = tblk + h * 64;
        // ---- LN: warp owns rows wid*4 .. wid*4+3; batch all 8 loads ----
        {
            float4 v0[4], v1[4];
            #pragma unroll
            for (int i = 0; i < 4; i++) {
                const float4* src =
                    (const float4*)(obs + (size_t)(t0 + wid * 4 + i) * C_);
                v0[i] = __ldcs(src + lane);
                v1[i] = __ldcs(src + lane + 32);
            }
            #pragma unroll
            for (int i = 0; i < 4; i++) {
                int r = wid * 4 + i;
                float s  = v0[i].x + v0[i].y + v0[i].z + v0[i].w
                         + v1[i].x + v1[i].y + v1[i].z + v1[i].w;
                float ss = v0[i].x*v0[i].x + v0[i].y*v0[i].y
                         + v0[i].z*v0[i].z + v0[i].w*v0[i].w
                         + v1[i].x*v1[i].x + v1[i].y*v1[i].y
                         + v1[i].z*v1[i].z + v1[i].w*v1[i].w;
                float2 red = warpRed2(s, ss);
                float mu  = red.x * (1.0f / 256.0f);
                float var = red.y * (1.0f / 256.0f) - mu * mu;
                float rsg = rsqrtf(var + 1e-5f);
                char* xr = (char*)ha + r * (XSTRIDE * 2);
                *(__nv_bfloat162*)(xr + (c0 + 0) * 2) =
                    __floats2bfloat162_rn((v0[i].x - mu) * rsg * nw0.x + nb0.x,
                                          (v0[i].y - mu) * rsg * nw0.y + nb0.y);
                *(__nv_bfloat162*)(xr + (c0 + 2) * 2) =
                    __floats2bfloat162_rn((v0[i].z - mu) * rsg * nw0.z + nb0.z,
                                          (v0[i].w - mu) * rsg * nw0.w + nb0.w);
                *(__nv_bfloat162*)(xr + (c0 + 128) * 2) =
                    __floats2bfloat162_rn((v1[i].x - mu) * rsg * nw1.x + nb1.x,
                                          (v1[i].y - mu) * rsg * nw1.y + nb1.y);
                *(__nv_bfloat162*)(xr + (c0 + 130) * 2) =
                    __floats2bfloat162_rn((v1[i].z - mu) * rsg * nw1.z + nb1.z,
                                          (v1[i].w - mu) * rsg * nw1.w + nb1.w);
            }
        }
        __syncthreads();

        // ---- MMA: m32 x n32 tile per warp ----
        {
            uint32_t aA = s2u(ha) + aAoff;
            uint32_t aB = aB0;
            float acc[2][4][4];
            #pragma unroll
            for (int mi = 0; mi < 2; mi++)
                #pragma unroll
                for (int nj = 0; nj < 4; nj++)
                    #pragma unroll
                    for (int e = 0; e < 4; e++) acc[mi][nj][e] = 0.f;

            #pragma unroll 1
            for (int s = 0; s < 16; s++) {
                uint32_t A0[4], A1[4], B0[4], B1[4];
                LDSM4(A0, aA);
                LDSM4(A1, aA + 16 * (XSTRIDE * 2));
                LDSM4(B0, aB);
                LDSM4(B1, aB + 16 * (XSTRIDE * 2));
                #pragma unroll
                for (int nj = 0; nj < 4; nj++) {
                    const uint32_t* Bf = (nj < 2) ? B0 : B1;
                    uint32_t b0 = Bf[(nj & 1) * 2];
                    uint32_t b1 = Bf[(nj & 1) * 2 + 1];
                    MMA_BF16(acc[0][nj], A0, b0, b1);
                    MMA_BF16(acc[1][nj], A1, b0, b1);
                }
                aA += 32;
                aB += 32;
            }

            const int rbase = t0 + wm2 * 32;
            #pragma unroll
            for (int mi = 0; mi < 2; mi++) {
                #pragma unroll
                for (int nj = 0; nj < 4; nj++) {
                    int c  = wn4 * 32 + nj * 8 + qcol;
                    int r0 = rbase + mi * 16 + qrow;
                    *(__nv_bfloat162*)(gout + (size_t)r0 * D_ + c) =
                        __floats2bfloat162_rn(acc[mi][nj][0], acc[mi][nj][1]);
                    *(__nv_bfloat162*)(gout + (size_t)(r0 + 8) * D_ + c) =
                        __floats2bfloat162_rn(acc[mi][nj][2], acc[mi][nj][3]);
                }
            }
        }
        __syncthreads();
    }
}

// ============================================================================
// LN stats helper (256-thread block, 128 live values in threads 0-127)
// ============================================================================
__device__ __forceinline__ void ln_stats(float x, float* r1, float* r2,
                                         float& mu, float& rs) {
    float2 red = warpRed2(x, x * x);
    int wid = threadIdx.x >> 5, lane = threadIdx.x & 31;
    if (lane == 0) { r1[wid] = red.x; r2[wid] = red.y; }
    __syncthreads();
    float Sm = 0.f, Sq = 0.f;
    #pragma unroll
    for (int i = 0; i < 8; i++) { Sm += r1[i]; Sq += r2[i]; }
    mu = Sm * (1.0f / 128.0f);
    float var = Sq * (1.0f / 128.0f) - mu * mu;
    rs = rsqrtf(var + 1e-5f);
}

// ============================================================================
// Kernel 2: slot init + q-pad zero + LN + q projection (fused). grid 160.
// ============================================================================
__global__ void k_sq_init(const float* __restrict__ noise, const float* __restrict__ smu,
                          const float* __restrict__ sls, const float* __restrict__ nsw,
                          const float* __restrict__ nsb, const float* __restrict__ Wq)
{
    __shared__ float sl[128];
    __shared__ float hm[128];
    __shared__ float hid[256];
    __shared__ float r1[8], r2[8];
    const int tid = threadIdx.x;
    const int b = blockIdx.x / 10;
    const int s = blockIdx.x % 10;

    if (tid < 128) {
        float v = smu[tid] + expf(sls[tid]) * noise[blockIdx.x * 128 + tid];
        g_slots[blockIdx.x * 128 + tid] = v;
        sl[tid] = v;
        if (s < 6)
            g_qb[b * 2048 + (10 + s) * 128 + tid] = __float2bfloat16(0.f);
    }
    __syncthreads();

    float x = (tid < 128) ? sl[tid] : 0.f;
    float mu, rs;
    ln_stats(x, r1, r2, mu, rs);
    if (tid < 128) hm[tid] = (x - mu) * rs * nsw[tid] + nsb[tid];
    __syncthreads();
    {
        int d = tid & 127, half = tid >> 7;
        const float* wq = Wq + half * 64 * 128;
        const float* hh = hm + half * 64;
        float a0 = 0, a1 = 0, a2 = 0, a3 = 0;
        #pragma unroll
        for (int c = 0; c < 64; c += 4) {
            a0 += hh[c + 0] * wq[(c + 0) * 128 + d];
            a1 += hh[c + 1] * wq[(c + 1) * 128 + d];
            a2 += hh[c + 2] * wq[(c + 2) * 128 + d];
            a3 += hh[c + 3] * wq[(c + 3) * 128 + d];
        }
        hid[tid] = (a0 + a1) + (a2 + a3);
    }
    __syncthreads();
    if (tid < 128)
        g_qb[b * 2048 + s * 128 + tid] =
            __float2bfloat16((hid[tid] + hid[tid + 128]) * QSCALE);
}

// ============================================================================
// Kernel 3: fused attention chunk (cp.async prefetch). grid (NCHUNK, B_).
// ============================================================================
#define TS 136
#define LSTR 132
#define ATT_SMEM (2*128*TS*2 + 16*TS*2 + 16*TS*2 + 16*LSTR*4)
__global__ __launch_bounds__(256, 2) void k_attn()
{
    extern __shared__ char sm2[];
    __nv_bfloat16* tileK = (__nv_bfloat16*)sm2;
    __nv_bfloat16* tileV = tileK + 128 * TS;
    __nv_bfloat16* Qs    = tileV + 128 * TS;
    __nv_bfloat16* aBm   = Qs + 16 * TS;
    float* Ls            = (float*)(aBm + 16 * TS);

    const int tid  = threadIdx.x;
    const int w    = tid >> 5;
    const int lane = tid & 31;
    const int ck   = blockIdx.x;
    const int b    = blockIdx.y;

    {
        const uint4* srcK = (const uint4*)(g_k + ((size_t)b * NPB + ck * CHUNK) * D_);
        const uint4* srcV = (const uint4*)(g_v + ((size_t)b * NPB + ck * CHUNK) * D_);
        const uint32_t dK = s2u(tileK), dV = s2u(tileV);
        #pragma unroll
        for (int i = 0; i < 8; i++) {
            int u = tid + i * 256;
            int row = u >> 4, c = u & 15;
            CPASYNC16(dK + row * (TS * 2) + c * 16, srcK + u);
        }
        CPCOMMIT();
        #pragma unroll
        for (int i = 0; i < 8; i++) {
            int u = tid + i * 256;
            int row = u >> 4, c = u & 15;
            CPASYNC16(dV + row * (TS * 2) + c * 16, srcV + u);
        }
        CPCOMMIT();
    }

    {
        int row = tid >> 4, c = tid & 15;
        *(uint4*)((char*)Qs + row * (TS * 2) + c * 16) =
            ((const uint4*)(g_qb + b * 2048))[tid];
    }
    if (tid < 102) {
        *(uint4*)((char*)aBm + 10 * (TS * 2) + tid * 16) = make_uint4(0, 0, 0, 0);
    }

    CPWAIT(1);
    __syncthreads();

    const int ga = lane >> 3, ra = lane & 7;
    const int qrow = lane >> 2, qcol = (lane & 3) * 2;
    const uint32_t baseA_q = s2u(Qs) +
        (uint32_t)(((ra + ((ga & 1) << 3)) * TS + ((ga >> 1) << 3)) * 2);
    const uint32_t baseB_k = s2u(tileK) +
        (uint32_t)(((w * 16 + ra + ((ga >> 1) << 3)) * TS + ((ga & 1) << 3)) * 2);

    {
        float lacc[2][4] = {{0,0,0,0},{0,0,0,0}};
        #pragma unroll
        for (int ks = 0; ks < 8; ks++) {
            uint32_t A[4], Bx[4];
            LDSM4(A, baseA_q + ks * 32);
            LDSM4(Bx, baseB_k + ks * 32);
            MMA_BF16(lacc[0], A, Bx[0], Bx[1]);
            MMA_BF16(lacc[1], A, Bx[2], Bx[3]);
        }
        #pragma unroll
        for (int nj = 0; nj < 2; nj++) {
            int t = w * 16 + nj * 8 + qcol;
            Ls[qrow * LSTR + t]           = lacc[nj][0];
            Ls[qrow * LSTR + t + 1]       = lacc[nj][1];
            Ls[(qrow + 8) * LSTR + t]     = lacc[nj][2];
            Ls[(qrow + 8) * LSTR + t + 1] = lacc[nj][3];
        }
    }
    __syncthreads();

    if (tid < 128) {
        float v[10]; float m = -1e30f;
        #pragma unroll
        for (int s = 0; s < 10; s++) { v[s] = Ls[s * LSTR + tid]; m = fmaxf(m, v[s]); }
        float sum = 0.f;
        #pragma unroll
        for (int s = 0; s < 10; s++) { v[s] = __expf(v[s] - m); sum += v[s]; }
        float inv = 1.0f / sum;
        #pragma unroll
        for (int s = 0; s < 10; s++) aBm[s * TS + tid] = __float2bfloat16(v[s] * inv);
    }
    __syncthreads();

    for (int s = w; s < 10; s += 8) {
        float p = bf(aBm[s * TS + lane]) + bf(aBm[s * TS + lane + 32])
                + bf(aBm[s * TS + lane + 64]) + bf(aBm[s * TS + lane + 96]);
        p = warpRed1(p);
        if (lane == 0) g_pden[(b * NCHUNK + ck) * S_ + s] = p;
    }

    CPWAIT(0);
    __syncthreads();

    {
        const uint32_t baseA_a = s2u(aBm) +
            (uint32_t)(((ra + ((ga & 1) << 3)) * TS + ((ga >> 1) << 3)) * 2);
        const uint32_t baseB_v = s2u(tileV) +
            (uint32_t)(((((ga & 1) << 3) + ra) * TS + w * 16 + ((ga >> 1) << 3)) * 2);
        float nacc[2][4] = {{0,0,0,0},{0,0,0,0}};
        #pragma unroll
        for (int ks = 0; ks < 8; ks++) {
            uint32_t A[4], Bt[4];
            LDSM4(A, baseA_a + ks * 32);
            LDSM4T(Bt, baseB_v + ks * (16 * TS * 2));
            MMA_BF16(nacc[0], A, Bt[0], Bt[1]);
            MMA_BF16(nacc[1], A, Bt[2], Bt[3]);
        }
        float* dst = g_pnum + (size_t)(b * NCHUNK + ck) * S_ * D_;
        #pragma unroll
        for (int nj = 0; nj < 2; nj++) {
            int d = w * 16 + nj * 8 + qcol;
            *(float2*)(dst + qrow * D_ + d) = make_float2(nacc[nj][0], nacc[nj][1]);
            if (qrow + 8 < 10)
                *(float2*)(dst + (qrow + 8) * D_ + d) = make_float2(nacc[nj][2], nacc[nj][3]);
        }
    }
}

// ============================================================================
// Kernel 4: slot update + q projection.  grid 160, 256 thr.  (R12-proven)
// ============================================================================
__global__ void k_slotq(const float* __restrict__ nmw, const float* __restrict__ nmb,
                        const float* __restrict__ w1, const float* __restrict__ b1,
                        const float* __restrict__ w2, const float* __restrict__ b2,
                        const float* __restrict__ nsw, const float* __restrict__ nsb,
                        const float* __restrict__ Wq)
{
    __shared__ float sl[128];
    __shared__ float hm[128];
    __shared__ float hid[256];
    __shared__ float r1[8], r2[8];
    __shared__ float sden;
    const int tid = threadIdx.x;
    const int b = blockIdx.x / 10;
    const int s = blockIdx.x % 10;

    if ((tid >> 5) == 4) {
        int lane = tid & 31;
        float p = g_pden[(b * NCHUNK + lane) * S_ + s];
        p = warpRed1(p);
        if (lane == 0) sden = p;
    }
    float u0 = 0, u1 = 0, u2 = 0, u3 = 0;
    if (tid < 128) {
        const float* src = g_pnum + ((size_t)(b * NCHUNK) * S_ + s) * D_ + tid;
        #pragma unroll
        for (int ch = 0; ch < NCHUNK; ch += 4) {
            u0 += __ldcs(src + (size_t)(ch + 0) * S_ * D_);
            u1 += __ldcs(src + (size_t)(ch + 1) * S_ * D_);
            u2 += __ldcs(src + (size_t)(ch + 2) * S_ * D_);
            u3 += __ldcs(src + (size_t)(ch + 3) * S_ * D_);
        }
    }
    __syncthreads();
    float slot_new = 0.f;
    if (tid < 128)
        slot_new = g_slots[(b * S_ + s) * D_ + tid]
                 + ((u0 + u1) + (u2 + u3)) / (sden + 1e-8f);
    float mu, rs;
    ln_stats(tid < 128 ? slot_new : 0.f, r1, r2, mu, rs);
    if (tid < 128) hm[tid] = (slot_new - mu) * rs * nmw[tid] + nmb[tid];
    __syncthreads();
    {
        float a0 = 0, a1 = 0, a2 = 0, a3 = 0;
        #pragma unroll
        for (int c = 0; c < 128; c += 4) {
            a0 += hm[c + 0] * w1[(c + 0) * 256 + tid];
            a1 += hm[c + 1] * w1[(c + 1) * 256 + tid];
            a2 += hm[c + 2] * w1[(c + 2) * 256 + tid];
            a3 += hm[c + 3] * w1[(c + 3) * 256 + tid];
        }
        hid[tid] = fmaxf(b1[tid] + (a0 + a1) + (a2 + a3), 0.f);
    }
    __syncthreads();
    if (tid < 128) {
        float o0 = 0, o1 = 0, o2 = 0, o3 = 0;
        #pragma unroll 16
        for (int j = 0; j < 256; j += 4) {
            o0 += hid[j + 0] * w2[(j + 0) * 128 + tid];
            o1 += hid[j + 1] * w2[(j + 1) * 128 + tid];
            o2 += hid[j + 2] * w2[(j + 2) * 128 + tid];
            o3 += hid[j + 3] * w2[(j + 3) * 128 + tid];
        }
        float sf = slot_new + b2[tid] + (o0 + o1) + (o2 + o3);
        sl[tid] = sf;
        g_slots[(b * S_ + s) * D_ + tid] = sf;
    }
    __syncthreads();

    float x = (tid < 128) ? sl[tid] : 0.f;
    ln_stats(x, r1, r2, mu, rs);
    if (tid < 128) hm[tid] = (x - mu) * rs * nsw[tid] + nsb[tid];
    __syncthreads();
    {
        int d = tid & 127, half = tid >> 7;
        const float* wq = Wq + half * 64 * 128;
        const float* hh = hm + half * 64;
        float a0 = 0, a1 = 0, a2 = 0, a3 = 0;
        #pragma unroll
        for (int c = 0; c < 64; c += 4) {
            a0 += hh[c + 0] * wq[(c + 0) * 128 + d];
            a1 += hh[c + 1] * wq[(c + 1) * 128 + d];
            a2 += hh[c + 2] * wq[(c + 2) * 128 + d];
            a3 += hh[c + 3] * wq[(c + 3) * 128 + d];
        }
        hid[tid] = (a0 + a1) + (a2 + a3);
    }
    __syncthreads();
    if (tid < 128)
        g_qb[b * 2048 + s * 128 + tid] =
            __float2bfloat16((hid[tid] + hid[tid + 128]) * QSCALE);
}

// ============================================================================
// Kernel 5: final update + heads.  grid 160, 256 thr.  (R12-proven)
// ============================================================================
__global__ void k_last(const float* __restrict__ nmw, const float* __restrict__ nmb,
                       const float* __restrict__ w1, const float* __restrict__ b1,
                       const float* __restrict__ w2, const float* __restrict__ b2,
                       const float* __restrict__ pw1, const float* __restrict__ pb1,
                       const float* __restrict__ pw2, const float* __restrict__ pb2,
                       const float* __restrict__ tw, const float* __restrict__ tb,
                       float* __restrict__ out)
{
    __shared__ float sl[128];
    __shared__ float hm[128];
    __shared__ float hid[256];
    __shared__ float r1[8], r2[8];
    __shared__ float sden;
    const int tid = threadIdx.x;
    const int b = blockIdx.x / 10;
    const int s = blockIdx.x % 10;

    if ((tid >> 5) == 4) {
        int lane = tid & 31;
        float p = g_pden[(b * NCHUNK + lane) * S_ + s];
        p = warpRed1(p);
        if (lane == 0) sden = p;
    }
    float u0 = 0, u1 = 0, u2 = 0, u3 = 0;
    if (tid < 128) {
        const float* src = g_pnum + ((size_t)(b * NCHUNK) * S_ + s) * D_ + tid;
        #pragma unroll
        for (int ch = 0; ch < NCHUNK; ch += 4) {
            u0 += __ldcs(src + (size_t)(ch + 0) * S_ * D_);
            u1 += __ldcs(src + (size_t)(ch + 1) * S_ * D_);
            u2 += __ldcs(src + (size_t)(ch + 2) * S_ * D_);
            u3 += __ldcs(src + (size_t)(ch + 3) * S_ * D_);
        }
    }
    __syncthreads();
    float slot_new = 0.f;
    if (tid < 128)
        slot_new = g_slots[(b * S_ + s) * D_ + tid]
                 + ((u0 + u1) + (u2 + u3)) / (sden + 1e-8f);
    float mu, rs;
    ln_stats(tid < 128 ? slot_new : 0.f, r1, r2, mu, rs);
    if (tid < 128) hm[tid] = (slot_new - mu) * rs * nmw[tid] + nmb[tid];
    __syncthreads();
    {
        float a0 = 0, a1 = 0, a2 = 0, a3 = 0;
        #pragma unroll
        for (int c = 0; c < 128; c += 4) {
            a0 += hm[c + 0] * w1[(c + 0) * 256 + tid];
            a1 += hm[c + 1] * w1[(c + 1) * 256 + tid];
            a2 += hm[c + 2] * w1[(c + 2) * 256 + tid];
            a3 += hm[c + 3] * w1[(c + 3) * 256 + tid];
        }
        hid[tid] = fmaxf(b1[tid] + (a0 + a1) + (a2 + a3), 0.f);
    }
    __syncthreads();
    if (tid < 128) {
        float o0 = 0, o1 = 0, o2 = 0, o3 = 0;
        #pragma unroll 16
        for (int j = 0; j < 256; j += 4) {
            o0 += hid[j + 0] * w2[(j + 0) * 128 + tid];
            o1 += hid[j + 1] * w2[(j + 1) * 128 + tid];
            o2 += hid[j + 2] * w2[(j + 2) * 128 + tid];
            o3 += hid[j + 3] * w2[(j + 3) * 128 + tid];
        }
        sl[tid] = slot_new + b2[tid] + (o0 + o1) + (o2 + o3);
    }
    __syncthreads();

    {
        float a0 = 0, a1 = 0, a2 = 0, a3 = 0;
        #pragma unroll
        for (int c = 0; c < 128; c += 4) {
            a0 += sl[c + 0] * pw1[(c + 0) * 256 + tid];
            a1 += sl[c + 1] * pw1[(c + 1) * 256 + tid];
            a2 += sl[c + 2] * pw1[(c + 2) * 256 + tid];
            a3 += sl[c + 3] * pw1[(c + 3) * 256 + tid];
        }
        hid[tid] = fmaxf(pb1[tid] + (a0 + a1) + (a2 + a3), 0.f);
    }
    __syncthreads();
    if (tid < 128) {
        float o0 = 0, o1 = 0, o2 = 0, o3 = 0;
        #pragma unroll 16
        for (int j = 0; j < 256; j += 4) {
            o0 += hid[j + 0] * pw2[(j + 0) * 128 + tid];
            o1 += hid[j + 1] * pw2[(j + 1) * 128 + tid];
            o2 += hid[j + 2] * pw2[(j + 2) * 128 + tid];
            o3 += hid[j + 3] * pw2[(j + 3) * 128 + tid];
        }
        out[blockIdx.x * 128 + tid] = pb2[tid] + (o0 + o1) + (o2 + o3);
    } else if (tid < 128 + T_) {
        int tt = tid - 128;
        float o = tb[tt];
        #pragma unroll 4
        for (int c = 0; c < 128; c++) o += sl[c] * tw[c * T_ + tt];
        out[B_ * S_ * D_ + blockIdx.x * T_ + tt] = o;
    }
}

// ============================================================================
extern "C" void kernel_launch(void* const* d_in, const int* in_sizes, int n_in,
                              void* d_out, int out_size)
{
    const float* obs  = (const float*)d_in[0];
    const float* noise= (const float*)d_in[1];
    const float* smu  = (const float*)d_in[2];
    const float* sls  = (const float*)d_in[3];
    const float* niw  = (const float*)d_in[4];
    const float* nib  = (const float*)d_in[5];
    const float* nsw  = (const float*)d_in[6];
    const float* nsb  = (const float*)d_in[7];
    const float* nmw  = (const float*)d_in[8];
    const float* nmb  = (const float*)d_in[9];
    const float* Wq   = (const float*)d_in[10];
    const float* Wk   = (const float*)d_in[11];
    const float* Wv   = (const float*)d_in[12];
    const float* mw1  = (const float*)d_in[13];
    const float* mb1  = (const float*)d_in[14];
    const float* mw2  = (const float*)d_in[15];
    const float* mb2  = (const float*)d_in[16];
    const float* pw1  = (const float*)d_in[17];
    const float* pb1  = (const float*)d_in[18];
    const float* pw2  = (const float*)d_in[19];
    const float* pb2  = (const float*)d_in[20];
    const float* tcw  = (const float*)d_in[21];
    const float* tcb  = (const float*)d_in[22];
    float* out = (float*)d_out;

    cudaFuncSetAttribute(k_ln_kv, cudaFuncAttributeMaxDynamicSharedMemorySize, SMEM1);
    cudaFuncSetAttribute(k_attn,  cudaFuncAttributeMaxDynamicSharedMemorySize, ATT_SMEM);

    // launch order: ncu capture (4th launch) lands on k_ln_kv
    k_prepk<<<D_, C_>>>(Wk);                                             // 1
    k_prepv<<<D_, C_>>>(Wv);                                             // 2
    k_sq_init<<<160, 256>>>(noise, smu, sls, nsw, nsb, Wq);              // 3
    k_ln_kv<<<NTOK / 512, 512, SMEM1>>>(obs, niw, nib);                  // 4 <- ncu
    dim3 g2(NCHUNK, B_);
    for (int it = 0; it < 3; it++) {
        k_attn<<<g2, 256, ATT_SMEM>>>();
        if (it < 2)
            k_slotq<<<160, 256>>>(nmw, nmb, mw1, mb1, mw2, mb2, nsw, nsb, Wq);
        else
            k_last<<<160, 256>>>(nmw, nmb, mw1, mb1, mw2, mb2,
                                 pw1, pb1, pw2, pb2, tcw, tcb, out);
    }
}

// round 15
// speedup vs baseline: 1.2107x; 1.0321x over previous
#include <cuda_runtime.h>
#include <cuda_bf16.h>
#include <cstdint>

#define B_    16
#define S_    10
#define D_    128
#define C_    256
#define NTOK  65536
#define NPB   4096
#define T_    20
#define CHUNK 128
#define NCHUNK 32
#define QSCALE 0.08838834764831845f

// ---- scratch ----
__device__ __nv_bfloat16 g_k[NTOK * D_];
__device__ __nv_bfloat16 g_v[NTOK * D_];
__device__ __nv_bfloat16 g_wkT[D_ * C_];
__device__ __nv_bfloat16 g_wvT[D_ * C_];
__device__ __nv_bfloat16 g_qb[B_ * 16 * D_];
__device__ float g_slots[B_ * S_ * D_];
__device__ float g_pnum[(size_t)B_ * NCHUNK * S_ * D_];
__device__ float g_pden[B_ * NCHUNK * S_];

__device__ __forceinline__ float2 warpRed2(float a, float b) {
    #pragma unroll
    for (int o = 16; o > 0; o >>= 1) {
        a += __shfl_xor_sync(0xffffffffu, a, o);
        b += __shfl_xor_sync(0xffffffffu, b, o);
    }
    return make_float2(a, b);
}
__device__ __forceinline__ float warpRed1(float a) {
    #pragma unroll
    for (int o = 16; o > 0; o >>= 1) a += __shfl_xor_sync(0xffffffffu, a, o);
    return a;
}

__device__ __forceinline__ uint32_t s2u(const void* p) {
    return (uint32_t)__cvta_generic_to_shared(p);
}
__device__ __forceinline__ float bf(const __nv_bfloat16 x) { return __bfloat162float(x); }

#define LDSM4(r, addr)                                                          \
    asm volatile("ldmatrix.sync.aligned.m8n8.x4.shared.b16 {%0,%1,%2,%3}, [%4];"\
                 : "=r"((r)[0]), "=r"((r)[1]), "=r"((r)[2]), "=r"((r)[3])       \
                 : "r"(addr))

#define LDSM4T(r, addr)                                                         \
    asm volatile("ldmatrix.sync.aligned.m8n8.x4.trans.shared.b16 {%0,%1,%2,%3}, [%4];"\
                 : "=r"((r)[0]), "=r"((r)[1]), "=r"((r)[2]), "=r"((r)[3])       \
                 : "r"(addr))

#define MMA_BF16(d, a, b0, b1)                                                  \
    asm volatile("mma.sync.aligned.m16n8k16.row.col.f32.bf16.bf16.f32 "         \
                 "{%0,%1,%2,%3}, {%4,%5,%6,%7}, {%8,%9}, {%0,%1,%2,%3};"        \
                 : "+f"((d)[0]), "+f"((d)[1]), "+f"((d)[2]), "+f"((d)[3])       \
                 : "r"((a)[0]), "r"((a)[1]), "r"((a)[2]), "r"((a)[3]),          \
                   "r"(b0), "r"(b1))

#define CPASYNC16(dst, src)                                                     \
    asm volatile("cp.async.cg.shared.global [%0], [%1], 16;"                    \
                 :: "r"(dst), "l"(src) : "memory")
#define CPCOMMIT() asm volatile("cp.async.commit_group;" ::: "memory")
#define CPWAIT(n)  asm volatile("cp.async.wait_group %0;" :: "n"(n) : "memory")

// ============================================================================
// Kernel 0: weight transpose + bf16 convert
// ============================================================================
__global__ void k_prep(const float* __restrict__ Wk, const float* __restrict__ Wv)
{
    int d = blockIdx.x, c = threadIdx.x;
    g_wkT[d * C_ + c] = __float2bfloat16(Wk[c * D_ + d]);
    g_wvT[d * C_ + c] = __float2bfloat16(Wv[c * D_ + d]);
}

// ============================================================================
// Kernel 1: fused LayerNorm + K,V projection, WARP-SPECIALIZED (R12-proven).
// 512 tokens/block, 512 threads, 128 blocks (single wave).
// Warps 8-15 (producers): LayerNorm 64-token half-tiles into double-buffered A.
// Warps 0-7 (consumers): 4 K-warps + 4 V-warps, each m32 x n64 MMA + epilogue.
// ============================================================================
#define XSTRIDE 264
#define SMEM1 (3 * 128 * XSTRIDE * 2)
__global__ __launch_bounds__(512, 1) void k_ln_kv(
    const float* __restrict__ obs, const float* __restrict__ niw,
    const float* __restrict__ nib)
{
    extern __shared__ char smx[];
    __nv_bfloat16* ha0 = (__nv_bfloat16*)smx;           // [64][264]
    __nv_bfloat16* ha1 = ha0 + 64 * XSTRIDE;
    __nv_bfloat16* wks = ha1 + 64 * XSTRIDE;            // [128][264]
    __nv_bfloat16* wvs = wks + 128 * XSTRIDE;

    const int tid  = threadIdx.x;
    const int wid  = tid >> 5;
    const int lane = tid & 31;
    const int tblk = blockIdx.x * 512;

    // stage bf16 transposed weights once per block (all 512 threads)
    {
        const uint4* gk4 = (const uint4*)g_wkT;
        const uint4* gv4 = (const uint4*)g_wvT;
        #pragma unroll
        for (int i = 0; i < 8; i++) {
            int u = tid + i * 512;
            int row = u >> 5, c = u & 31;
            *(uint4*)((char*)wks + row * (XSTRIDE * 2) + c * 16) = gk4[u];
            *(uint4*)((char*)wvs + row * (XSTRIDE * 2) + c * 16) = gv4[u];
        }
    }

    if (wid >= 8) {
        // ================= PRODUCER: LayerNorm =================
        const int p  = wid - 8;                 // 0..7, rows p*8..p*8+7 of the half
        const int c0 = lane * 4;
        float4 nw0 = *(const float4*)(niw + c0);
        float4 nw1 = *(const float4*)(niw + c0 + 128);
        float4 nb0 = *(const float4*)(nib + c0);
        float4 nb1 = *(const float4*)(nib + c0 + 128);

        #pragma unroll 1
        for (int h = -1; h < 8; h++) {
            if (h < 7) {
                const int hh = h + 1;
                __nv_bfloat16* buf = (hh & 1) ? ha1 : ha0;
                const int t0 = tblk + hh * 64;
                #pragma unroll
                for (int i = 0; i < 8; i++) {
                    int r = p * 8 + i;
                    const float4* src = (const float4*)(obs + (size_t)(t0 + r) * C_);
                    float4 v0 = __ldcs(src + lane);
                    float4 v1 = __ldcs(src + lane + 32);
                    float s  = v0.x + v0.y + v0.z + v0.w + v1.x + v1.y + v1.z + v1.w;
                    float ss = v0.x*v0.x + v0.y*v0.y + v0.z*v0.z + v0.w*v0.w
                             + v1.x*v1.x + v1.y*v1.y + v1.z*v1.z + v1.w*v1.w;
                    float2 red = warpRed2(s, ss);
                    float mu  = red.x * (1.0f / 256.0f);
                    float var = red.y * (1.0f / 256.0f) - mu * mu;
                    float rsg = rsqrtf(var + 1e-5f);
                    char* xr = (char*)buf + r * (XSTRIDE * 2);
                    *(__nv_bfloat162*)(xr + (c0 + 0) * 2) =
                        __floats2bfloat162_rn((v0.x - mu) * rsg * nw0.x + nb0.x,
                                              (v0.y - mu) * rsg * nw0.y + nb0.y);
                    *(__nv_bfloat162*)(xr + (c0 + 2) * 2) =
                        __floats2bfloat162_rn((v0.z - mu) * rsg * nw0.z + nb0.z,
                                              (v0.w - mu) * rsg * nw0.w + nb0.w);
                    *(__nv_bfloat162*)(xr + (c0 + 128) * 2) =
                        __floats2bfloat162_rn((v1.x - mu) * rsg * nw1.x + nb1.x,
                                              (v1.y - mu) * rsg * nw1.y + nb1.y);
                    *(__nv_bfloat162*)(xr + (c0 + 130) * 2) =
                        __floats2bfloat162_rn((v1.z - mu) * rsg * nw1.z + nb1.z,
                                              (v1.w - mu) * rsg * nw1.w + nb1.w);
                }
            }
            __syncthreads();
        }
    } else {
        // ================= CONSUMER: MMA + epilogue =================
        const int mat = wid >> 2;          // 0 = K (warps 0-3), 1 = V (warps 4-7)
        const int wm  = wid & 1;           // m half (32 rows of 64)
        const int wn  = (wid >> 1) & 1;    // n half (64 cols of 128)
        const __nv_bfloat16* wsm = mat ? wvs : wks;
        const int ga = lane >> 3, ra = lane & 7;
        const uint32_t aB0 = s2u(wsm) +
            (uint32_t)(((wn * 64 + ra + ((ga >> 1) << 3)) * XSTRIDE + ((ga & 1) << 3)) * 2);
        const uint32_t aAoff =
            (uint32_t)(((wm * 32 + ra + ((ga & 1) << 3)) * XSTRIDE + ((ga >> 1) << 3)) * 2);
        const int qrow = lane >> 2;
        const int qcol = (lane & 3) * 2;
        __nv_bfloat16* gout = mat ? g_v : g_k;

        __syncthreads();    // matches producers' prologue barrier
        #pragma unroll 1
        for (int h = 0; h < 8; h++) {
            const __nv_bfloat16* abuf = (h & 1) ? ha1 : ha0;
            uint32_t aA = s2u(abuf) + aAoff;
            uint32_t aB = aB0;

            float acc[2][8][4];
            #pragma unroll
            for (int mi = 0; mi < 2; mi++)
                #pragma unroll
                for (int nj = 0; nj < 8; nj++)
                    #pragma unroll
                    for (int e = 0; e < 4; e++) acc[mi][nj][e] = 0.f;

            #pragma unroll 1
            for (int s = 0; s < 16; s++) {
                uint32_t A0[4], A1[4], Bx[4][4];
                LDSM4(A0, aA);
                LDSM4(A1, aA + 16 * (XSTRIDE * 2));
                #pragma unroll
                for (int j = 0; j < 4; j++)
                    LDSM4(Bx[j], aB + j * 16 * (XSTRIDE * 2));
                #pragma unroll
                for (int nj = 0; nj < 8; nj++) {
                    uint32_t b0 = Bx[nj >> 1][(nj & 1) * 2];
                    uint32_t b1 = Bx[nj >> 1][(nj & 1) * 2 + 1];
                    MMA_BF16(acc[0][nj], A0, b0, b1);
                    MMA_BF16(acc[1][nj], A1, b0, b1);
                }
                aA += 32;
                aB += 32;
            }

            const int rbase = tblk + h * 64 + wm * 32;
            #pragma unroll
            for (int mi = 0; mi < 2; mi++) {
                #pragma unroll
                for (int nj = 0; nj < 8; nj++) {
                    int c  = wn * 64 + nj * 8 + qcol;
                    int r0 = rbase + mi * 16 + qrow;
                    *(__nv_bfloat162*)(gout + (size_t)r0 * D_ + c) =
                        __floats2bfloat162_rn(acc[mi][nj][0], acc[mi][nj][1]);
                    *(__nv_bfloat162*)(gout + (size_t)(r0 + 8) * D_ + c) =
                        __floats2bfloat162_rn(acc[mi][nj][2], acc[mi][nj][3]);
                }
            }
            __syncthreads();
        }
    }
}

// ============================================================================
// LN stats helper (256-thread block, 128 live values)
// ============================================================================
__device__ __forceinline__ void ln_stats(float x, float* r1, float* r2,
                                         float& mu, float& rs) {
    float2 red = warpRed2(x, x * x);
    int wid = threadIdx.x >> 5, lane = threadIdx.x & 31;
    if (lane == 0) { r1[wid] = red.x; r2[wid] = red.y; }
    __syncthreads();
    float Sm = 0.f, Sq = 0.f;
    #pragma unroll
    for (int i = 0; i < 8; i++) { Sm += r1[i]; Sq += r2[i]; }
    mu = Sm * (1.0f / 128.0f);
    float var = Sq * (1.0f / 128.0f) - mu * mu;
    rs = rsqrtf(var + 1e-5f);
}

// ============================================================================
// Kernel 2: slot init + q-pad zero + LN + q projection (fused). grid 160.
// ============================================================================
__global__ void k_sq_init(const float* __restrict__ noise, const float* __restrict__ smu,
                          const float* __restrict__ sls, const float* __restrict__ nsw,
                          const float* __restrict__ nsb, const float* __restrict__ Wq)
{
    __shared__ float sl[128];
    __shared__ float hm[128];
    __shared__ float hid[256];
    __shared__ float r1[8], r2[8];
    const int tid = threadIdx.x;
    const int b = blockIdx.x / 10;
    const int s = blockIdx.x % 10;

    if (tid < 128) {
        float v = smu[tid] + expf(sls[tid]) * noise[blockIdx.x * 128 + tid];
        g_slots[blockIdx.x * 128 + tid] = v;
        sl[tid] = v;
        if (s < 6)
            g_qb[b * 2048 + (10 + s) * 128 + tid] = __float2bfloat16(0.f);
    }
    __syncthreads();

    float x = (tid < 128) ? sl[tid] : 0.f;
    float mu, rs;
    ln_stats(x, r1, r2, mu, rs);
    if (tid < 128) hm[tid] = (x - mu) * rs * nsw[tid] + nsb[tid];
    __syncthreads();
    {
        int d = tid & 127, half = tid >> 7;
        const float* wq = Wq + half * 64 * 128;
        const float* hh = hm + half * 64;
        float a0 = 0, a1 = 0, a2 = 0, a3 = 0;
        #pragma unroll
        for (int c = 0; c < 64; c += 4) {
            a0 += hh[c + 0] * wq[(c + 0) * 128 + d];
            a1 += hh[c + 1] * wq[(c + 1) * 128 + d];
            a2 += hh[c + 2] * wq[(c + 2) * 128 + d];
            a3 += hh[c + 3] * wq[(c + 3) * 128 + d];
        }
        hid[tid] = (a0 + a1) + (a2 + a3);
    }
    __syncthreads();
    if (tid < 128)
        g_qb[b * 2048 + s * 128 + tid] =
            __float2bfloat16((hid[tid] + hid[tid + 128]) * QSCALE);
}

// ============================================================================
// Kernel 3: fused attention chunk, cp.async K/V prefetch (R12-proven).
// grid (NCHUNK, B_), 256 threads, 2 CTAs/SM.
// ============================================================================
#define TS 136
#define LSTR 132
#define ATT_SMEM (2*128*TS*2 + 16*TS*2 + 16*TS*2 + 16*LSTR*4)
__global__ __launch_bounds__(256, 2) void k_attn()
{
    extern __shared__ char sm2[];
    __nv_bfloat16* tileK = (__nv_bfloat16*)sm2;
    __nv_bfloat16* tileV = tileK + 128 * TS;
    __nv_bfloat16* Qs    = tileV + 128 * TS;
    __nv_bfloat16* aBm   = Qs + 16 * TS;
    float* Ls            = (float*)(aBm + 16 * TS);

    const int tid  = threadIdx.x;
    const int w    = tid >> 5;
    const int lane = tid & 31;
    const int ck   = blockIdx.x;
    const int b    = blockIdx.y;

    {
        const uint4* srcK = (const uint4*)(g_k + ((size_t)b * NPB + ck * CHUNK) * D_);
        const uint4* srcV = (const uint4*)(g_v + ((size_t)b * NPB + ck * CHUNK) * D_);
        const uint32_t dK = s2u(tileK), dV = s2u(tileV);
        #pragma unroll
        for (int i = 0; i < 8; i++) {
            int u = tid + i * 256;
            int row = u >> 4, c = u & 15;
            CPASYNC16(dK + row * (TS * 2) + c * 16, srcK + u);
        }
        CPCOMMIT();
        #pragma unroll
        for (int i = 0; i < 8; i++) {
            int u = tid + i * 256;
            int row = u >> 4, c = u & 15;
            CPASYNC16(dV + row * (TS * 2) + c * 16, srcV + u);
        }
        CPCOMMIT();
    }

    {
        int row = tid >> 4, c = tid & 15;
        *(uint4*)((char*)Qs + row * (TS * 2) + c * 16) =
            ((const uint4*)(g_qb + b * 2048))[tid];
    }
    if (tid < 102) {
        *(uint4*)((char*)aBm + 10 * (TS * 2) + tid * 16) = make_uint4(0, 0, 0, 0);
    }

    CPWAIT(1);
    __syncthreads();

    const int ga = lane >> 3, ra = lane & 7;
    const int qrow = lane >> 2, qcol = (lane & 3) * 2;
    const uint32_t baseA_q = s2u(Qs) +
        (uint32_t)(((ra + ((ga & 1) << 3)) * TS + ((ga >> 1) << 3)) * 2);
    const uint32_t baseB_k = s2u(tileK) +
        (uint32_t)(((w * 16 + ra + ((ga >> 1) << 3)) * TS + ((ga & 1) << 3)) * 2);

    {
        float lacc[2][4] = {{0,0,0,0},{0,0,0,0}};
        #pragma unroll
        for (int ks = 0; ks < 8; ks++) {
            uint32_t A[4], Bx[4];
            LDSM4(A, baseA_q + ks * 32);
            LDSM4(Bx, baseB_k + ks * 32);
            MMA_BF16(lacc[0], A, Bx[0], Bx[1]);
            MMA_BF16(lacc[1], A, Bx[2], Bx[3]);
        }
        #pragma unroll
        for (int nj = 0; nj < 2; nj++) {
            int t = w * 16 + nj * 8 + qcol;
            Ls[qrow * LSTR + t]           = lacc[nj][0];
            Ls[qrow * LSTR + t + 1]       = lacc[nj][1];
            Ls[(qrow + 8) * LSTR + t]     = lacc[nj][2];
            Ls[(qrow + 8) * LSTR + t + 1] = lacc[nj][3];
        }
    }
    __syncthreads();

    if (tid < 128) {
        float v[10]; float m = -1e30f;
        #pragma unroll
        for (int s = 0; s < 10; s++) { v[s] = Ls[s * LSTR + tid]; m = fmaxf(m, v[s]); }
        float sum = 0.f;
        #pragma unroll
        for (int s = 0; s < 10; s++) { v[s] = __expf(v[s] - m); sum += v[s]; }
        float inv = 1.0f / sum;
        #pragma unroll
        for (int s = 0; s < 10; s++) aBm[s * TS + tid] = __float2bfloat16(v[s] * inv);
    }
    __syncthreads();

    for (int s = w; s < 10; s += 8) {
        float p = bf(aBm[s * TS + lane]) + bf(aBm[s * TS + lane + 32])
                + bf(aBm[s * TS + lane + 64]) + bf(aBm[s * TS + lane + 96]);
        p = warpRed1(p);
        if (lane == 0) g_pden[(b * NCHUNK + ck) * S_ + s] = p;
    }

    CPWAIT(0);
    __syncthreads();

    {
        const uint32_t baseA_a = s2u(aBm) +
            (uint32_t)(((ra + ((ga & 1) << 3)) * TS + ((ga >> 1) << 3)) * 2);
        const uint32_t baseB_v = s2u(tileV) +
            (uint32_t)(((((ga & 1) << 3) + ra) * TS + w * 16 + ((ga >> 1) << 3)) * 2);
        float nacc[2][4] = {{0,0,0,0},{0,0,0,0}};
        #pragma unroll
        for (int ks = 0; ks < 8; ks++) {
            uint32_t A[4], Bt[4];
            LDSM4(A, baseA_a + ks * 32);
            LDSM4T(Bt, baseB_v + ks * (16 * TS * 2));
            MMA_BF16(nacc[0], A, Bt[0], Bt[1]);
            MMA_BF16(nacc[1], A, Bt[2], Bt[3]);
        }
        float* dst = g_pnum + (size_t)(b * NCHUNK + ck) * S_ * D_;
        #pragma unroll
        for (int nj = 0; nj < 2; nj++) {
            int d = w * 16 + nj * 8 + qcol;
            *(float2*)(dst + qrow * D_ + d) = make_float2(nacc[nj][0], nacc[nj][1]);
            if (qrow + 8 < 10)
                *(float2*)(dst + (qrow + 8) * D_ + d) = make_float2(nacc[nj][2], nacc[nj][3]);
        }
    }
}

// ============================================================================
// Kernel 4: slot update + q projection.  grid 160, 256 thr.  (R12-proven)
// ============================================================================
__global__ void k_slotq(const float* __restrict__ nmw, const float* __restrict__ nmb,
                        const float* __restrict__ w1, const float* __restrict__ b1,
                        const float* __restrict__ w2, const float* __restrict__ b2,
                        const float* __restrict__ nsw, const float* __restrict__ nsb,
                        const float* __restrict__ Wq)
{
    __shared__ float sl[128];
    __shared__ float hm[128];
    __shared__ float hid[256];
    __shared__ float r1[8], r2[8];
    __shared__ float sden;
    const int tid = threadIdx.x;
    const int b = blockIdx.x / 10;
    const int s = blockIdx.x % 10;

    if ((tid >> 5) == 4) {
        int lane = tid & 31;
        float p = g_pden[(b * NCHUNK + lane) * S_ + s];
        p = warpRed1(p);
        if (lane == 0) sden = p;
    }
    float u0 = 0, u1 = 0, u2 = 0, u3 = 0;
    if (tid < 128) {
        const float* src = g_pnum + ((size_t)(b * NCHUNK) * S_ + s) * D_ + tid;
        #pragma unroll
        for (int ch = 0; ch < NCHUNK; ch += 4) {
            u0 += __ldcs(src + (size_t)(ch + 0) * S_ * D_);
            u1 += __ldcs(src + (size_t)(ch + 1) * S_ * D_);
            u2 += __ldcs(src + (size_t)(ch + 2) * S_ * D_);
            u3 += __ldcs(src + (size_t)(ch + 3) * S_ * D_);
        }
    }
    __syncthreads();
    float slot_new = 0.f;
    if (tid < 128)
        slot_new = g_slots[(b * S_ + s) * D_ + tid]
                 + ((u0 + u1) + (u2 + u3)) / (sden + 1e-8f);
    float mu, rs;
    ln_stats(tid < 128 ? slot_new : 0.f, r1, r2, mu, rs);
    if (tid < 128) hm[tid] = (slot_new - mu) * rs * nmw[tid] + nmb[tid];
    __syncthreads();
    {
        float a0 = 0, a1 = 0, a2 = 0, a3 = 0;
        #pragma unroll
        for (int c = 0; c < 128; c += 4) {
            a0 += hm[c + 0] * w1[(c + 0) * 256 + tid];
            a1 += hm[c + 1] * w1[(c + 1) * 256 + tid];
            a2 += hm[c + 2] * w1[(c + 2) * 256 + tid];
            a3 += hm[c + 3] * w1[(c + 3) * 256 + tid];
        }
        hid[tid] = fmaxf(b1[tid] + (a0 + a1) + (a2 + a3), 0.f);
    }
    __syncthreads();
    if (tid < 128) {
        float o0 = 0, o1 = 0, o2 = 0, o3 = 0;
        #pragma unroll 16
        for (int j = 0; j < 256; j += 4) {
            o0 += hid[j + 0] * w2[(j + 0) * 128 + tid];
            o1 += hid[j + 1] * w2[(j + 1) * 128 + tid];
            o2 += hid[j + 2] * w2[(j + 2) * 128 + tid];
            o3 += hid[j + 3] * w2[(j + 3) * 128 + tid];
        }
        float sf = slot_new + b2[tid] + (o0 + o1) + (o2 + o3);
        sl[tid] = sf;
        g_slots[(b * S_ + s) * D_ + tid] = sf;
    }
    __syncthreads();

    float x = (tid < 128) ? sl[tid] : 0.f;
    ln_stats(x, r1, r2, mu, rs);
    if (tid < 128) hm[tid] = (x - mu) * rs * nsw[tid] + nsb[tid];
    __syncthreads();
    {
        int d = tid & 127, half = tid >> 7;
        const float* wq = Wq + half * 64 * 128;
        const float* hh = hm + half * 64;
        float a0 = 0, a1 = 0, a2 = 0, a3 = 0;
        #pragma unroll
        for (int c = 0; c < 64; c += 4) {
            a0 += hh[c + 0] * wq[(c + 0) * 128 + d];
            a1 += hh[c + 1] * wq[(c + 1) * 128 + d];
            a2 += hh[c + 2] * wq[(c + 2) * 128 + d];
            a3 += hh[c + 3] * wq[(c + 3) * 128 + d];
        }
        hid[tid] = (a0 + a1) + (a2 + a3);
    }
    __syncthreads();
    if (tid < 128)
        g_qb[b * 2048 + s * 128 + tid] =
            __float2bfloat16((hid[tid] + hid[tid + 128]) * QSCALE);
}

// ============================================================================
// Kernel 5: final update + heads.  grid 160, 256 thr.  (R12-proven)
// ============================================================================
__global__ void k_last(const float* __restrict__ nmw, const float* __restrict__ nmb,
                       const float* __restrict__ w1, const float* __restrict__ b1,
                       const float* __restrict__ w2, const float* __restrict__ b2,
                       const float* __restrict__ pw1, const float* __restrict__ pb1,
                       const float* __restrict__ pw2, const float* __restrict__ pb2,
                       const float* __restrict__ tw, const float* __restrict__ tb,
                       float* __restrict__ out)
{
    __shared__ float sl[128];
    __shared__ float hm[128];
    __shared__ float hid[256];
    __shared__ float r1[8], r2[8];
    __shared__ float sden;
    const int tid = threadIdx.x;
    const int b = blockIdx.x / 10;
    const int s = blockIdx.x % 10;

    if ((tid >> 5) == 4) {
        int lane = tid & 31;
        float p = g_pden[(b * NCHUNK + lane) * S_ + s];
        p = warpRed1(p);
        if (lane == 0) sden = p;
    }
    float u0 = 0, u1 = 0, u2 = 0, u3 = 0;
    if (tid < 128) {
        const float* src = g_pnum + ((size_t)(b * NCHUNK) * S_ + s) * D_ + tid;
        #pragma unroll
        for (int ch = 0; ch < NCHUNK; ch += 4) {
            u0 += __ldcs(src + (size_t)(ch + 0) * S_ * D_);
            u1 += __ldcs(src + (size_t)(ch + 1) * S_ * D_);
            u2 += __ldcs(src + (size_t)(ch + 2) * S_ * D_);
            u3 += __ldcs(src + (size_t)(ch + 3) * S_ * D_);
        }
    }
    __syncthreads();
    float slot_new = 0.f;
    if (tid < 128)
        slot_new = g_slots[(b * S_ + s) * D_ + tid]
                 + ((u0 + u1) + (u2 + u3)) / (sden + 1e-8f);
    float mu, rs;
    ln_stats(tid < 128 ? slot_new : 0.f, r1, r2, mu, rs);
    if (tid < 128) hm[tid] = (slot_new - mu) * rs * nmw[tid] + nmb[tid];
    __syncthreads();
    {
        float a0 = 0, a1 = 0, a2 = 0, a3 = 0;
        #pragma unroll
        for (int c = 0; c < 128; c += 4) {
            a0 += hm[c + 0] * w1[(c + 0) * 256 + tid];
            a1 += hm[c + 1] * w1[(c + 1) * 256 + tid];
            a2 += hm[c + 2] * w1[(c + 2) * 256 + tid];
            a3 += hm[c + 3] * w1[(c + 3) * 256 + tid];
        }
        hid[tid] = fmaxf(b1[tid] + (a0 + a1) + (a2 + a3), 0.f);
    }
    __syncthreads();
    if (tid < 128) {
        float o0 = 0, o1 = 0, o2 = 0, o3 = 0;
        #pragma unroll 16
        for (int j = 0; j < 256; j += 4) {
            o0 += hid[j + 0] * w2[(j + 0) * 128 + tid];
            o1 += hid[j + 1] * w2[(j + 1) * 128 + tid];
            o2 += hid[j + 2] * w2[(j + 2) * 128 + tid];
            o3 += hid[j + 3] * w2[(j + 3) * 128 + tid];
        }
        sl[tid] = slot_new + b2[tid] + (o0 + o1) + (o2 + o3);
    }
    __syncthreads();

    {
        float a0 = 0, a1 = 0, a2 = 0, a3 = 0;
        #pragma unroll
        for (int c = 0; c < 128; c += 4) {
            a0 += sl[c + 0] * pw1[(c + 0) * 256 + tid];
            a1 += sl[c + 1] * pw1[(c + 1) * 256 + tid];
            a2 += sl[c + 2] * pw1[(c + 2) * 256 + tid];
            a3 += sl[c + 3] * pw1[(c + 3) * 256 + tid];
        }
        hid[tid] = fmaxf(pb1[tid] + (a0 + a1) + (a2 + a3), 0.f);
    }
    __syncthreads();
    if (tid < 128) {
        float o0 = 0, o1 = 0, o2 = 0, o3 = 0;
        #pragma unroll 16
        for (int j = 0; j < 256; j += 4) {
            o0 += hid[j + 0] * pw2[(j + 0) * 128 + tid];
            o1 += hid[j + 1] * pw2[(j + 1) * 128 + tid];
            o2 += hid[j + 2] * pw2[(j + 2) * 128 + tid];
            o3 += hid[j + 3] * pw2[(j + 3) * 128 + tid];
        }
        out[blockIdx.x * 128 + tid] = pb2[tid] + (o0 + o1) + (o2 + o3);
    } else if (tid < 128 + T_) {
        int tt = tid - 128;
        float o = tb[tt];
        #pragma unroll 4
        for (int c = 0; c < 128; c++) o += sl[c] * tw[c * T_ + tt];
        out[B_ * S_ * D_ + blockIdx.x * T_ + tt] = o;
    }
}

// ============================================================================
extern "C" void kernel_launch(void* const* d_in, const int* in_sizes, int n_in,
                              void* d_out, int out_size)
{
    const float* obs  = (const float*)d_in[0];
    const float* noise= (const float*)d_in[1];
    const float* smu  = (const float*)d_in[2];
    const float* sls  = (const float*)d_in[3];
    const float* niw  = (const float*)d_in[4];
    const float* nib  = (const float*)d_in[5];
    const float* nsw  = (const float*)d_in[6];
    const float* nsb  = (const float*)d_in[7];
    const float* nmw  = (const float*)d_in[8];
    const float* nmb  = (const float*)d_in[9];
    const float* Wq   = (const float*)d_in[10];
    const float* Wk   = (const float*)d_in[11];
    const float* Wv   = (const float*)d_in[12];
    const float* mw1  = (const float*)d_in[13];
    const float* mb1  = (const float*)d_in[14];
    const float* mw2  = (const float*)d_in[15];
    const float* mb2  = (const float*)d_in[16];
    const float* pw1  = (const float*)d_in[17];
    const float* pb1  = (const float*)d_in[18];
    const float* pw2  = (const float*)d_in[19];
    const float* pb2  = (const float*)d_in[20];
    const float* tcw  = (const float*)d_in[21];
    const float* tcb  = (const float*)d_in[22];
    float* out = (float*)d_out;

    cudaFuncSetAttribute(k_ln_kv, cudaFuncAttributeMaxDynamicSharedMemorySize, SMEM1);
    cudaFuncSetAttribute(k_attn,  cudaFuncAttributeMaxDynamicSharedMemorySize, ATT_SMEM);

    k_prep<<<D_, C_>>>(Wk, Wv);                                          // 1
    k_sq_init<<<160, 256>>>(noise, smu, sls, nsw, nsb, Wq);              // 2
    k_ln_kv<<<NTOK / 512, 512, SMEM1>>>(obs, niw, nib);                  // 3
    dim3 g2(NCHUNK, B_);
    for (int it = 0; it < 3; it++) {
        k_attn<<<g2, 256, ATT_SMEM>>>();                                 // 4 <- ncu
        if (it < 2)
            k_slotq<<<160, 256>>>(nmw, nmb, mw1, mb1, mw2, mb2, nsw, nsb, Wq);
        else
            k_last<<<160, 256>>>(nmw, nmb, mw1, mb1, mw2, mb2,
                                 pw1, pb1, pw2, pb2, tcw, tcb, out);
    }
}

// round 16
// speedup vs baseline: 1.2301x; 1.0160x over previous
#include <cuda_runtime.h>
#include <cuda_bf16.h>
#include <cstdint>

#define B_    16
#define S_    10
#define D_    128
#define C_    256
#define NTOK  65536
#define NPB   4096
#define T_    20
#define CHUNK 128
#define NCHUNK 32
#define QSCALE 0.08838834764831845f

// ---- scratch ----
__device__ __nv_bfloat16 g_k[NTOK * D_];
__device__ __nv_bfloat16 g_v[NTOK * D_];
__device__ __nv_bfloat16 g_wkT[D_ * C_];
__device__ __nv_bfloat16 g_wvT[D_ * C_];
__device__ __nv_bfloat16 g_qb[B_ * 16 * D_];
__device__ float g_slots[B_ * S_ * D_];
__device__ float g_pnum[(size_t)B_ * NCHUNK * S_ * D_];
__device__ float g_pden[B_ * NCHUNK * S_];

__device__ __forceinline__ float2 warpRed2(float a, float b) {
    #pragma unroll
    for (int o = 16; o > 0; o >>= 1) {
        a += __shfl_xor_sync(0xffffffffu, a, o);
        b += __shfl_xor_sync(0xffffffffu, b, o);
    }
    return make_float2(a, b);
}
__device__ __forceinline__ float warpRed1(float a) {
    #pragma unroll
    for (int o = 16; o > 0; o >>= 1) a += __shfl_xor_sync(0xffffffffu, a, o);
    return a;
}

__device__ __forceinline__ uint32_t s2u(const void* p) {
    return (uint32_t)__cvta_generic_to_shared(p);
}
__device__ __forceinline__ float bf(const __nv_bfloat16 x) { return __bfloat162float(x); }

#define LDSM4(r, addr)                                                          \
    asm volatile("ldmatrix.sync.aligned.m8n8.x4.shared.b16 {%0,%1,%2,%3}, [%4];"\
                 : "=r"((r)[0]), "=r"((r)[1]), "=r"((r)[2]), "=r"((r)[3])       \
                 : "r"(addr))

#define LDSM4T(r, addr)                                                         \
    asm volatile("ldmatrix.sync.aligned.m8n8.x4.trans.shared.b16 {%0,%1,%2,%3}, [%4];"\
                 : "=r"((r)[0]), "=r"((r)[1]), "=r"((r)[2]), "=r"((r)[3])       \
                 : "r"(addr))

#define MMA_BF16(d, a, b0, b1)                                                  \
    asm volatile("mma.sync.aligned.m16n8k16.row.col.f32.bf16.bf16.f32 "         \
                 "{%0,%1,%2,%3}, {%4,%5,%6,%7}, {%8,%9}, {%0,%1,%2,%3};"        \
                 : "+f"((d)[0]), "+f"((d)[1]), "+f"((d)[2]), "+f"((d)[3])       \
                 : "r"((a)[0]), "r"((a)[1]), "r"((a)[2]), "r"((a)[3]),          \
                   "r"(b0), "r"(b1))

#define CPASYNC16(dst, src)                                                     \
    asm volatile("cp.async.cg.shared.global [%0], [%1], 16;"                    \
                 :: "r"(dst), "l"(src) : "memory")
#define CPCOMMIT() asm volatile("cp.async.commit_group;" ::: "memory")
#define CPWAIT(n)  asm volatile("cp.async.wait_group %0;" :: "n"(n) : "memory")

// ============================================================================
// Kernel 0: weight transpose + bf16 convert
// ============================================================================
__global__ void k_prep(const float* __restrict__ Wk, const float* __restrict__ Wv)
{
    int d = blockIdx.x, c = threadIdx.x;
    g_wkT[d * C_ + c] = __float2bfloat16(Wk[c * D_ + d]);
    g_wvT[d * C_ + c] = __float2bfloat16(Wv[c * D_ + d]);
}

// ============================================================================
// Kernel 1: fused LayerNorm + K,V projection, WARP-SPECIALIZED (R12-proven).
// ============================================================================
#define XSTRIDE 264
#define SMEM1 (3 * 128 * XSTRIDE * 2)
__global__ __launch_bounds__(512, 1) void k_ln_kv(
    const float* __restrict__ obs, const float* __restrict__ niw,
    const float* __restrict__ nib)
{
    extern __shared__ char smx[];
    __nv_bfloat16* ha0 = (__nv_bfloat16*)smx;           // [64][264]
    __nv_bfloat16* ha1 = ha0 + 64 * XSTRIDE;
    __nv_bfloat16* wks = ha1 + 64 * XSTRIDE;            // [128][264]
    __nv_bfloat16* wvs = wks + 128 * XSTRIDE;

    const int tid  = threadIdx.x;
    const int wid  = tid >> 5;
    const int lane = tid & 31;
    const int tblk = blockIdx.x * 512;

    {
        const uint4* gk4 = (const uint4*)g_wkT;
        const uint4* gv4 = (const uint4*)g_wvT;
        #pragma unroll
        for (int i = 0; i < 8; i++) {
            int u = tid + i * 512;
            int row = u >> 5, c = u & 31;
            *(uint4*)((char*)wks + row * (XSTRIDE * 2) + c * 16) = gk4[u];
            *(uint4*)((char*)wvs + row * (XSTRIDE * 2) + c * 16) = gv4[u];
        }
    }

    if (wid >= 8) {
        // ================= PRODUCER: LayerNorm =================
        const int p  = wid - 8;
        const int c0 = lane * 4;
        float4 nw0 = *(const float4*)(niw + c0);
        float4 nw1 = *(const float4*)(niw + c0 + 128);
        float4 nb0 = *(const float4*)(nib + c0);
        float4 nb1 = *(const float4*)(nib + c0 + 128);

        #pragma unroll 1
        for (int h = -1; h < 8; h++) {
            if (h < 7) {
                const int hh = h + 1;
                __nv_bfloat16* buf = (hh & 1) ? ha1 : ha0;
                const int t0 = tblk + hh * 64;
                #pragma unroll
                for (int i = 0; i < 8; i++) {
                    int r = p * 8 + i;
                    const float4* src = (const float4*)(obs + (size_t)(t0 + r) * C_);
                    float4 v0 = __ldcs(src + lane);
                    float4 v1 = __ldcs(src + lane + 32);
                    float s  = v0.x + v0.y + v0.z + v0.w + v1.x + v1.y + v1.z + v1.w;
                    float ss = v0.x*v0.x + v0.y*v0.y + v0.z*v0.z + v0.w*v0.w
                             + v1.x*v1.x + v1.y*v1.y + v1.z*v1.z + v1.w*v1.w;
                    float2 red = warpRed2(s, ss);
                    float mu  = red.x * (1.0f / 256.0f);
                    float var = red.y * (1.0f / 256.0f) - mu * mu;
                    float rsg = rsqrtf(var + 1e-5f);
                    char* xr = (char*)buf + r * (XSTRIDE * 2);
                    *(__nv_bfloat162*)(xr + (c0 + 0) * 2) =
                        __floats2bfloat162_rn((v0.x - mu) * rsg * nw0.x + nb0.x,
                                              (v0.y - mu) * rsg * nw0.y + nb0.y);
                    *(__nv_bfloat162*)(xr + (c0 + 2) * 2) =
                        __floats2bfloat162_rn((v0.z - mu) * rsg * nw0.z + nb0.z,
                                              (v0.w - mu) * rsg * nw0.w + nb0.w);
                    *(__nv_bfloat162*)(xr + (c0 + 128) * 2) =
                        __floats2bfloat162_rn((v1.x - mu) * rsg * nw1.x + nb1.x,
                                              (v1.y - mu) * rsg * nw1.y + nb1.y);
                    *(__nv_bfloat162*)(xr + (c0 + 130) * 2) =
                        __floats2bfloat162_rn((v1.z - mu) * rsg * nw1.z + nb1.z,
                                              (v1.w - mu) * rsg * nw1.w + nb1.w);
                }
            }
            __syncthreads();
        }
    } else {
        // ================= CONSUMER: MMA + epilogue =================
        const int mat = wid >> 2;
        const int wm  = wid & 1;
        const int wn  = (wid >> 1) & 1;
        const __nv_bfloat16* wsm = mat ? wvs : wks;
        const int ga = lane >> 3, ra = lane & 7;
        const uint32_t aB0 = s2u(wsm) +
            (uint32_t)(((wn * 64 + ra + ((ga >> 1) << 3)) * XSTRIDE + ((ga & 1) << 3)) * 2);
        const uint32_t aAoff =
            (uint32_t)(((wm * 32 + ra + ((ga & 1) << 3)) * XSTRIDE + ((ga >> 1) << 3)) * 2);
        const int qrow = lane >> 2;
        const int qcol = (lane & 3) * 2;
        __nv_bfloat16* gout = mat ? g_v : g_k;

        __syncthreads();
        #pragma unroll 1
        for (int h = 0; h < 8; h++) {
            const __nv_bfloat16* abuf = (h & 1) ? ha1 : ha0;
            uint32_t aA = s2u(abuf) + aAoff;
            uint32_t aB = aB0;

            float acc[2][8][4];
            #pragma unroll
            for (int mi = 0; mi < 2; mi++)
                #pragma unroll
                for (int nj = 0; nj < 8; nj++)
                    #pragma unroll
                    for (int e = 0; e < 4; e++) acc[mi][nj][e] = 0.f;

            #pragma unroll 1
            for (int s = 0; s < 16; s++) {
                uint32_t A0[4], A1[4], Bx[4][4];
                LDSM4(A0, aA);
                LDSM4(A1, aA + 16 * (XSTRIDE * 2));
                #pragma unroll
                for (int j = 0; j < 4; j++)
                    LDSM4(Bx[j], aB + j * 16 * (XSTRIDE * 2));
                #pragma unroll
                for (int nj = 0; nj < 8; nj++) {
                    uint32_t b0 = Bx[nj >> 1][(nj & 1) * 2];
                    uint32_t b1 = Bx[nj >> 1][(nj & 1) * 2 + 1];
                    MMA_BF16(acc[0][nj], A0, b0, b1);
                    MMA_BF16(acc[1][nj], A1, b0, b1);
                }
                aA += 32;
                aB += 32;
            }

            const int rbase = tblk + h * 64 + wm * 32;
            #pragma unroll
            for (int mi = 0; mi < 2; mi++) {
                #pragma unroll
                for (int nj = 0; nj < 8; nj++) {
                    int c  = wn * 64 + nj * 8 + qcol;
                    int r0 = rbase + mi * 16 + qrow;
                    *(__nv_bfloat162*)(gout + (size_t)r0 * D_ + c) =
                        __floats2bfloat162_rn(acc[mi][nj][0], acc[mi][nj][1]);
                    *(__nv_bfloat162*)(gout + (size_t)(r0 + 8) * D_ + c) =
                        __floats2bfloat162_rn(acc[mi][nj][2], acc[mi][nj][3]);
                }
            }
            __syncthreads();
        }
    }
}

// ============================================================================
// LN stats helper (256-thread block, 128 live values)
// ============================================================================
__device__ __forceinline__ void ln_stats(float x, float* r1, float* r2,
                                         float& mu, float& rs) {
    float2 red = warpRed2(x, x * x);
    int wid = threadIdx.x >> 5, lane = threadIdx.x & 31;
    if (lane == 0) { r1[wid] = red.x; r2[wid] = red.y; }
    __syncthreads();
    float Sm = 0.f, Sq = 0.f;
    #pragma unroll
    for (int i = 0; i < 8; i++) { Sm += r1[i]; Sq += r2[i]; }
    mu = Sm * (1.0f / 128.0f);
    float var = Sq * (1.0f / 128.0f) - mu * mu;
    rs = rsqrtf(var + 1e-5f);
}

// ============================================================================
// Kernel 2: slot init + q-pad zero + LN + q projection (fused). grid 160.
// ============================================================================
__global__ void k_sq_init(const float* __restrict__ noise, const float* __restrict__ smu,
                          const float* __restrict__ sls, const float* __restrict__ nsw,
                          const float* __restrict__ nsb, const float* __restrict__ Wq)
{
    __shared__ float sl[128];
    __shared__ float hm[128];
    __shared__ float hid[256];
    __shared__ float r1[8], r2[8];
    const int tid = threadIdx.x;
    const int b = blockIdx.x / 10;
    const int s = blockIdx.x % 10;

    if (tid < 128) {
        float v = smu[tid] + expf(sls[tid]) * noise[blockIdx.x * 128 + tid];
        g_slots[blockIdx.x * 128 + tid] = v;
        sl[tid] = v;
        if (s < 6)
            g_qb[b * 2048 + (10 + s) * 128 + tid] = __float2bfloat16(0.f);
    }
    __syncthreads();

    float x = (tid < 128) ? sl[tid] : 0.f;
    float mu, rs;
    ln_stats(x, r1, r2, mu, rs);
    if (tid < 128) hm[tid] = (x - mu) * rs * nsw[tid] + nsb[tid];
    __syncthreads();
    {
        int d = tid & 127, half = tid >> 7;
        const float* wq = Wq + half * 64 * 128;
        const float* hh = hm + half * 64;
        float a0 = 0, a1 = 0, a2 = 0, a3 = 0;
        #pragma unroll
        for (int c = 0; c < 64; c += 4) {
            a0 += hh[c + 0] * wq[(c + 0) * 128 + d];
            a1 += hh[c + 1] * wq[(c + 1) * 128 + d];
            a2 += hh[c + 2] * wq[(c + 2) * 128 + d];
            a3 += hh[c + 3] * wq[(c + 3) * 128 + d];
        }
        hid[tid] = (a0 + a1) + (a2 + a3);
    }
    __syncthreads();
    if (tid < 128)
        g_qb[b * 2048 + s * 128 + tid] =
            __float2bfloat16((hid[tid] + hid[tid + 128]) * QSCALE);
}

// ============================================================================
// Kernel 3: fused attention, TWO chunks per CTA with staggered cp.async:
// commit order K0,V0,K1,V1; K1 issued after chunk-0 softmax (tileK dead),
// V1 issued after chunk-0 numerator (tileV dead). grid (16,16) = 256 blocks
// -> SINGLE WAVE at 2 CTAs/SM. Q load + pad-zero amortized over 2 chunks.
// ============================================================================
#define TS 136
#define LSTR 132
#define ATT_SMEM (2*128*TS*2 + 16*TS*2 + 16*TS*2 + 16*LSTR*4)
__global__ __launch_bounds__(256, 2) void k_attn()
{
    extern __shared__ char sm2[];
    __nv_bfloat16* tileK = (__nv_bfloat16*)sm2;
    __nv_bfloat16* tileV = tileK + 128 * TS;
    __nv_bfloat16* Qs    = tileV + 128 * TS;
    __nv_bfloat16* aBm   = Qs + 16 * TS;
    float* Ls            = (float*)(aBm + 16 * TS);

    const int tid  = threadIdx.x;
    const int w    = tid >> 5;
    const int lane = tid & 31;
    const int ck0  = blockIdx.x * 2;
    const int b    = blockIdx.y;

    const uint32_t dK = s2u(tileK), dV = s2u(tileV);
    const uint4* srcK0 = (const uint4*)(g_k + ((size_t)b * NPB + ck0 * CHUNK) * D_);
    const uint4* srcV0 = (const uint4*)(g_v + ((size_t)b * NPB + ck0 * CHUNK) * D_);

    // ---- issue K0 (group), V0 (group) ----
    #pragma unroll
    for (int i = 0; i < 8; i++) {
        int u = tid + i * 256;
        int row = u >> 4, c = u & 15;
        CPASYNC16(dK + row * (TS * 2) + c * 16, srcK0 + u);
    }
    CPCOMMIT();
    #pragma unroll
    for (int i = 0; i < 8; i++) {
        int u = tid + i * 256;
        int row = u >> 4, c = u & 15;
        CPASYNC16(dV + row * (TS * 2) + c * 16, srcV0 + u);
    }
    CPCOMMIT();

    // Q + attn pad zero (once for both chunks)
    {
        int row = tid >> 4, c = tid & 15;
        *(uint4*)((char*)Qs + row * (TS * 2) + c * 16) =
            ((const uint4*)(g_qb + b * 2048))[tid];
    }
    if (tid < 102) {
        *(uint4*)((char*)aBm + 10 * (TS * 2) + tid * 16) = make_uint4(0, 0, 0, 0);
    }

    CPWAIT(1);      // K0 ready
    __syncthreads();

    const int ga = lane >> 3, ra = lane & 7;
    const int qrow = lane >> 2, qcol = (lane & 3) * 2;
    const uint32_t baseA_q = s2u(Qs) +
        (uint32_t)(((ra + ((ga & 1) << 3)) * TS + ((ga >> 1) << 3)) * 2);
    const uint32_t baseB_k = s2u(tileK) +
        (uint32_t)(((w * 16 + ra + ((ga >> 1) << 3)) * TS + ((ga & 1) << 3)) * 2);
    const uint32_t baseA_a = s2u(aBm) +
        (uint32_t)(((ra + ((ga & 1) << 3)) * TS + ((ga >> 1) << 3)) * 2);
    const uint32_t baseB_v = s2u(tileV) +
        (uint32_t)(((((ga & 1) << 3) + ra) * TS + w * 16 + ((ga >> 1) << 3)) * 2);

    #pragma unroll 1
    for (int cc = 0; cc < 2; cc++) {
        const int ck = ck0 + cc;

        // ---- logits MMA: l[s][t] ----
        {
            float lacc[2][4] = {{0,0,0,0},{0,0,0,0}};
            #pragma unroll
            for (int ks = 0; ks < 8; ks++) {
                uint32_t A[4], Bx[4];
                LDSM4(A, baseA_q + ks * 32);
                LDSM4(Bx, baseB_k + ks * 32);
                MMA_BF16(lacc[0], A, Bx[0], Bx[1]);
                MMA_BF16(lacc[1], A, Bx[2], Bx[3]);
            }
            #pragma unroll
            for (int nj = 0; nj < 2; nj++) {
                int t = w * 16 + nj * 8 + qcol;
                Ls[qrow * LSTR + t]           = lacc[nj][0];
                Ls[qrow * LSTR + t + 1]       = lacc[nj][1];
                Ls[(qrow + 8) * LSTR + t]     = lacc[nj][2];
                Ls[(qrow + 8) * LSTR + t + 1] = lacc[nj][3];
            }
        }
        __syncthreads();

        // ---- softmax over 10 slots per token ----
        if (tid < 128) {
            float v[10]; float m = -1e30f;
            #pragma unroll
            for (int s = 0; s < 10; s++) { v[s] = Ls[s * LSTR + tid]; m = fmaxf(m, v[s]); }
            float sum = 0.f;
            #pragma unroll
            for (int s = 0; s < 10; s++) { v[s] = __expf(v[s] - m); sum += v[s]; }
            float inv = 1.0f / sum;
            #pragma unroll
            for (int s = 0; s < 10; s++) aBm[s * TS + tid] = __float2bfloat16(v[s] * inv);
        }
        __syncthreads();

        // ---- chunk 0 only: tileK now dead -> prefetch K1 ----
        if (cc == 0) {
            const uint4* srcK1 =
                (const uint4*)(g_k + ((size_t)b * NPB + (ck0 + 1) * CHUNK) * D_);
            #pragma unroll
            for (int i = 0; i < 8; i++) {
                int u = tid + i * 256;
                int row = u >> 4, c = u & 15;
                CPASYNC16(dK + row * (TS * 2) + c * 16, srcK1 + u);
            }
            CPCOMMIT();
        }

        // ---- denominators ----
        for (int s = w; s < 10; s += 8) {
            float p = bf(aBm[s * TS + lane]) + bf(aBm[s * TS + lane + 32])
                    + bf(aBm[s * TS + lane + 64]) + bf(aBm[s * TS + lane + 96]);
            p = warpRed1(p);
            if (lane == 0) g_pden[(b * NCHUNK + ck) * S_ + s] = p;
        }

        // wait for V(current): cc==0 -> outstanding {V0,K1}, wait 1 -> V0 done
        //                      cc==1 -> outstanding {V1},    wait 0 -> V1 done
        if (cc == 0) { CPWAIT(1); } else { CPWAIT(0); }
        __syncthreads();

        // ---- numerator MMA ----
        {
            float nacc[2][4] = {{0,0,0,0},{0,0,0,0}};
            #pragma unroll
            for (int ks = 0; ks < 8; ks++) {
                uint32_t A[4], Bt[4];
                LDSM4(A, baseA_a + ks * 32);
                LDSM4T(Bt, baseB_v + ks * (16 * TS * 2));
                MMA_BF16(nacc[0], A, Bt[0], Bt[1]);
                MMA_BF16(nacc[1], A, Bt[2], Bt[3]);
            }
            float* dst = g_pnum + (size_t)(b * NCHUNK + ck) * S_ * D_;
            #pragma unroll
            for (int nj = 0; nj < 2; nj++) {
                int d = w * 16 + nj * 8 + qcol;
                *(float2*)(dst + qrow * D_ + d) = make_float2(nacc[nj][0], nacc[nj][1]);
                if (qrow + 8 < 10)
                    *(float2*)(dst + (qrow + 8) * D_ + d) =
                        make_float2(nacc[nj][2], nacc[nj][3]);
            }
        }

        // ---- chunk 0 only: tileV dead after numerator -> prefetch V1, wait K1 ----
        if (cc == 0) {
            __syncthreads();     // all warps done reading tileV
            const uint4* srcV1 =
                (const uint4*)(g_v + ((size_t)b * NPB + (ck0 + 1) * CHUNK) * D_);
            #pragma unroll
            for (int i = 0; i < 8; i++) {
                int u = tid + i * 256;
                int row = u >> 4, c = u & 15;
                CPASYNC16(dV + row * (TS * 2) + c * 16, srcV1 + u);
            }
            CPCOMMIT();
            CPWAIT(1);           // outstanding {K1,V1} -> K1 done
            __syncthreads();
        }
    }
}

// ============================================================================
// Kernel 4: slot update + q projection.  grid 160, 256 thr.  (R12-proven)
// ============================================================================
__global__ void k_slotq(const float* __restrict__ nmw, const float* __restrict__ nmb,
                        const float* __restrict__ w1, const float* __restrict__ b1,
                        const float* __restrict__ w2, const float* __restrict__ b2,
                        const float* __restrict__ nsw, const float* __restrict__ nsb,
                        const float* __restrict__ Wq)
{
    __shared__ float sl[128];
    __shared__ float hm[128];
    __shared__ float hid[256];
    __shared__ float r1[8], r2[8];
    __shared__ float sden;
    const int tid = threadIdx.x;
    const int b = blockIdx.x / 10;
    const int s = blockIdx.x % 10;

    if ((tid >> 5) == 4) {
        int lane = tid & 31;
        float p = g_pden[(b * NCHUNK + lane) * S_ + s];
        p = warpRed1(p);
        if (lane == 0) sden = p;
    }
    float u0 = 0, u1 = 0, u2 = 0, u3 = 0;
    if (tid < 128) {
        const float* src = g_pnum + ((size_t)(b * NCHUNK) * S_ + s) * D_ + tid;
        #pragma unroll
        for (int ch = 0; ch < NCHUNK; ch += 4) {
            u0 += __ldcs(src + (size_t)(ch + 0) * S_ * D_);
            u1 += __ldcs(src + (size_t)(ch + 1) * S_ * D_);
            u2 += __ldcs(src + (size_t)(ch + 2) * S_ * D_);
            u3 += __ldcs(src + (size_t)(ch + 3) * S_ * D_);
        }
    }
    __syncthreads();
    float slot_new = 0.f;
    if (tid < 128)
        slot_new = g_slots[(b * S_ + s) * D_ + tid]
                 + ((u0 + u1) + (u2 + u3)) / (sden + 1e-8f);
    float mu, rs;
    ln_stats(tid < 128 ? slot_new : 0.f, r1, r2, mu, rs);
    if (tid < 128) hm[tid] = (slot_new - mu) * rs * nmw[tid] + nmb[tid];
    __syncthreads();
    {
        float a0 = 0, a1 = 0, a2 = 0, a3 = 0;
        #pragma unroll
        for (int c = 0; c < 128; c += 4) {
            a0 += hm[c + 0] * w1[(c + 0) * 256 + tid];
            a1 += hm[c + 1] * w1[(c + 1) * 256 + tid];
            a2 += hm[c + 2] * w1[(c + 2) * 256 + tid];
            a3 += hm[c + 3] * w1[(c + 3) * 256 + tid];
        }
        hid[tid] = fmaxf(b1[tid] + (a0 + a1) + (a2 + a3), 0.f);
    }
    __syncthreads();
    if (tid < 128) {
        float o0 = 0, o1 = 0, o2 = 0, o3 = 0;
        #pragma unroll 16
        for (int j = 0; j < 256; j += 4) {
            o0 += hid[j + 0] * w2[(j + 0) * 128 + tid];
            o1 += hid[j + 1] * w2[(j + 1) * 128 + tid];
            o2 += hid[j + 2] * w2[(j + 2) * 128 + tid];
            o3 += hid[j + 3] * w2[(j + 3) * 128 + tid];
        }
        float sf = slot_new + b2[tid] + (o0 + o1) + (o2 + o3);
        sl[tid] = sf;
        g_slots[(b * S_ + s) * D_ + tid] = sf;
    }
    __syncthreads();

    float x = (tid < 128) ? sl[tid] : 0.f;
    ln_stats(x, r1, r2, mu, rs);
    if (tid < 128) hm[tid] = (x - mu) * rs * nsw[tid] + nsb[tid];
    __syncthreads();
    {
        int d = tid & 127, half = tid >> 7;
        const float* wq = Wq + half * 64 * 128;
        const float* hh = hm + half * 64;
        float a0 = 0, a1 = 0, a2 = 0, a3 = 0;
        #pragma unroll
        for (int c = 0; c < 64; c += 4) {
            a0 += hh[c + 0] * wq[(c + 0) * 128 + d];
            a1 += hh[c + 1] * wq[(c + 1) * 128 + d];
            a2 += hh[c + 2] * wq[(c + 2) * 128 + d];
            a3 += hh[c + 3] * wq[(c + 3) * 128 + d];
        }
        hid[tid] = (a0 + a1) + (a2 + a3);
    }
    __syncthreads();
    if (tid < 128)
        g_qb[b * 2048 + s * 128 + tid] =
            __float2bfloat16((hid[tid] + hid[tid + 128]) * QSCALE);
}

// ============================================================================
// Kernel 5: final update + heads.  grid 160, 256 thr.  (R12-proven)
// ============================================================================
__global__ void k_last(const float* __restrict__ nmw, const float* __restrict__ nmb,
                       const float* __restrict__ w1, const float* __restrict__ b1,
                       const float* __restrict__ w2, const float* __restrict__ b2,
                       const float* __restrict__ pw1, const float* __restrict__ pb1,
                       const float* __restrict__ pw2, const float* __restrict__ pb2,
                       const float* __restrict__ tw, const float* __restrict__ tb,
                       float* __restrict__ out)
{
    __shared__ float sl[128];
    __shared__ float hm[128];
    __shared__ float hid[256];
    __shared__ float r1[8], r2[8];
    __shared__ float sden;
    const int tid = threadIdx.x;
    const int b = blockIdx.x / 10;
    const int s = blockIdx.x % 10;

    if ((tid >> 5) == 4) {
        int lane = tid & 31;
        float p = g_pden[(b * NCHUNK + lane) * S_ + s];
        p = warpRed1(p);
        if (lane == 0) sden = p;
    }
    float u0 = 0, u1 = 0, u2 = 0, u3 = 0;
    if (tid < 128) {
        const float* src = g_pnum + ((size_t)(b * NCHUNK) * S_ + s) * D_ + tid;
        #pragma unroll
        for (int ch = 0; ch < NCHUNK; ch += 4) {
            u0 += __ldcs(src + (size_t)(ch + 0) * S_ * D_);
            u1 += __ldcs(src + (size_t)(ch + 1) * S_ * D_);
            u2 += __ldcs(src + (size_t)(ch + 2) * S_ * D_);
            u3 += __ldcs(src + (size_t)(ch + 3) * S_ * D_);
        }
    }
    __syncthreads();
    float slot_new = 0.f;
    if (tid < 128)
        slot_new = g_slots[(b * S_ + s) * D_ + tid]
                 + ((u0 + u1) + (u2 + u3)) / (sden + 1e-8f);
    float mu, rs;
    ln_stats(tid < 128 ? slot_new : 0.f, r1, r2, mu, rs);
    if (tid < 128) hm[tid] = (slot_new - mu) * rs * nmw[tid] + nmb[tid];
    __syncthreads();
    {
        float a0 = 0, a1 = 0, a2 = 0, a3 = 0;
        #pragma unroll
        for (int c = 0; c < 128; c += 4) {
            a0 += hm[c + 0] * w1[(c + 0) * 256 + tid];
            a1 += hm[c + 1] * w1[(c + 1) * 256 + tid];
            a2 += hm[c + 2] * w1[(c + 2) * 256 + tid];
            a3 += hm[c + 3] * w1[(c + 3) * 256 + tid];
        }
        hid[tid] = fmaxf(b1[tid] + (a0 + a1) + (a2 + a3), 0.f);
    }
    __syncthreads();
    if (tid < 128) {
        float o0 = 0, o1 = 0, o2 = 0, o3 = 0;
        #pragma unroll 16
        for (int j = 0; j < 256; j += 4) {
            o0 += hid[j + 0] * w2[(j + 0) * 128 + tid];
            o1 += hid[j + 1] * w2[(j + 1) * 128 + tid];
            o2 += hid[j + 2] * w2[(j + 2) * 128 + tid];
            o3 += hid[j + 3] * w2[(j + 3) * 128 + tid];
        }
        sl[tid] = slot_new + b2[tid] + (o0 + o1) + (o2 + o3);
    }
    __syncthreads();

    {
        float a0 = 0, a1 = 0, a2 = 0, a3 = 0;
        #pragma unroll
        for (int c = 0; c < 128; c += 4) {
            a0 += sl[c + 0] * pw1[(c + 0) * 256 + tid];
            a1 += sl[c + 1] * pw1[(c + 1) * 256 + tid];
            a2 += sl[c + 2] * pw1[(c + 2) * 256 + tid];
            a3 += sl[c + 3] * pw1[(c + 3) * 256 + tid];
        }
        hid[tid] = fmaxf(pb1[tid] + (a0 + a1) + (a2 + a3), 0.f);
    }
    __syncthreads();
    if (tid < 128) {
        float o0 = 0, o1 = 0, o2 = 0, o3 = 0;
        #pragma unroll 16
        for (int j = 0; j < 256; j += 4) {
            o0 += hid[j + 0] * pw2[(j + 0) * 128 + tid];
            o1 += hid[j + 1] * pw2[(j + 1) * 128 + tid];
            o2 += hid[j + 2] * pw2[(j + 2) * 128 + tid];
            o3 += hid[j + 3] * pw2[(j + 3) * 128 + tid];
        }
        out[blockIdx.x * 128 + tid] = pb2[tid] + (o0 + o1) + (o2 + o3);
    } else if (tid < 128 + T_) {
        int tt = tid - 128;
        float o = tb[tt];
        #pragma unroll 4
        for (int c = 0; c < 128; c++) o += sl[c] * tw[c * T_ + tt];
        out[B_ * S_ * D_ + blockIdx.x * T_ + tt] = o;
    }
}

// ============================================================================
extern "C" void kernel_launch(void* const* d_in, const int* in_sizes, int n_in,
                              void* d_out, int out_size)
{
    const float* obs  = (const float*)d_in[0];
    const float* noise= (const float*)d_in[1];
    const float* smu  = (const float*)d_in[2];
    const float* sls  = (const float*)d_in[3];
    const float* niw  = (const float*)d_in[4];
    const float* nib  = (const float*)d_in[5];
    const float* nsw  = (const float*)d_in[6];
    const float* nsb  = (const float*)d_in[7];
    const float* nmw  = (const float*)d_in[8];
    const float* nmb  = (const float*)d_in[9];
    const float* Wq   = (const float*)d_in[10];
    const float* Wk   = (const float*)d_in[11];
    const float* Wv   = (const float*)d_in[12];
    const float* mw1  = (const float*)d_in[13];
    const float* mb1  = (const float*)d_in[14];
    const float* mw2  = (const float*)d_in[15];
    const float* mb2  = (const float*)d_in[16];
    const float* pw1  = (const float*)d_in[17];
    const float* pb1  = (const float*)d_in[18];
    const float* pw2  = (const float*)d_in[19];
    const float* pb2  = (const float*)d_in[20];
    const float* tcw  = (const float*)d_in[21];
    const float* tcb  = (const float*)d_in[22];
    float* out = (float*)d_out;

    cudaFuncSetAttribute(k_ln_kv, cudaFuncAttributeMaxDynamicSharedMemorySize, SMEM1);
    cudaFuncSetAttribute(k_attn,  cudaFuncAttributeMaxDynamicSharedMemorySize, ATT_SMEM);

    k_prep<<<D_, C_>>>(Wk, Wv);                                          // 1
    k_sq_init<<<160, 256>>>(noise, smu, sls, nsw, nsb, Wq);              // 2
    k_ln_kv<<<NTOK / 512, 512, SMEM1>>>(obs, niw, nib);                  // 3
    dim3 g2(NCHUNK / 2, B_);
    for (int it = 0; it < 3; it++) {
        k_attn<<<g2, 256, ATT_SMEM>>>();                                 // 4 <- ncu
        if (it < 2)
            k_slotq<<<160, 256>>>(nmw, nmb, mw1, mb1, mw2, mb2, nsw, nsb, Wq);
        else
            k_last<<<160, 256>>>(nmw, nmb, mw1, mb1, mw2, mb2,
                                 pw1, pb1, pw2, pb2, tcw, tcb, out);
    }
}

// round 17
// speedup vs baseline: 1.2545x; 1.0198x over previous
#include <cuda_runtime.h>
#include <cuda_bf16.h>
#include <cstdint>

#define B_    16
#define S_    10
#define D_    128
#define C_    256
#define NTOK  65536
#define NPB   4096
#define T_    20
#define CHUNK 128
#define NCHUNK 32
#define NCH2  16            /* partials per batch after 2-chunk accumulation */
#define QSCALE 0.08838834764831845f

// ---- scratch ----
__device__ __nv_bfloat16 g_k[NTOK * D_];
__device__ __nv_bfloat16 g_v[NTOK * D_];
__device__ __nv_bfloat16 g_wkT[D_ * C_];
__device__ __nv_bfloat16 g_wvT[D_ * C_];
__device__ __nv_bfloat16 g_qb[B_ * 16 * D_];
__device__ float g_slots[B_ * S_ * D_];
__device__ float g_pnum[(size_t)B_ * NCH2 * S_ * D_];
__device__ float g_pden[B_ * NCH2 * S_];

__device__ __forceinline__ float2 warpRed2(float a, float b) {
    #pragma unroll
    for (int o = 16; o > 0; o >>= 1) {
        a += __shfl_xor_sync(0xffffffffu, a, o);
        b += __shfl_xor_sync(0xffffffffu, b, o);
    }
    return make_float2(a, b);
}
__device__ __forceinline__ float warpRed1(float a) {
    #pragma unroll
    for (int o = 16; o > 0; o >>= 1) a += __shfl_xor_sync(0xffffffffu, a, o);
    return a;
}

__device__ __forceinline__ uint32_t s2u(const void* p) {
    return (uint32_t)__cvta_generic_to_shared(p);
}
__device__ __forceinline__ float bf(const __nv_bfloat16 x) { return __bfloat162float(x); }

#define LDSM4(r, addr)                                                          \
    asm volatile("ldmatrix.sync.aligned.m8n8.x4.shared.b16 {%0,%1,%2,%3}, [%4];"\
                 : "=r"((r)[0]), "=r"((r)[1]), "=r"((r)[2]), "=r"((r)[3])       \
                 : "r"(addr))

#define LDSM4T(r, addr)                                                         \
    asm volatile("ldmatrix.sync.aligned.m8n8.x4.trans.shared.b16 {%0,%1,%2,%3}, [%4];"\
                 : "=r"((r)[0]), "=r"((r)[1]), "=r"((r)[2]), "=r"((r)[3])       \
                 : "r"(addr))

#define MMA_BF16(d, a, b0, b1)                                                  \
    asm volatile("mma.sync.aligned.m16n8k16.row.col.f32.bf16.bf16.f32 "         \
                 "{%0,%1,%2,%3}, {%4,%5,%6,%7}, {%8,%9}, {%0,%1,%2,%3};"        \
                 : "+f"((d)[0]), "+f"((d)[1]), "+f"((d)[2]), "+f"((d)[3])       \
                 : "r"((a)[0]), "r"((a)[1]), "r"((a)[2]), "r"((a)[3]),          \
                   "r"(b0), "r"(b1))

#define CPASYNC16(dst, src)                                                     \
    asm volatile("cp.async.cg.shared.global [%0], [%1], 16;"                    \
                 :: "r"(dst), "l"(src) : "memory")
#define CPCOMMIT() asm volatile("cp.async.commit_group;" ::: "memory")
#define CPWAIT(n)  asm volatile("cp.async.wait_group %0;" :: "n"(n) : "memory")

// ============================================================================
// LN stats helper (256-thread block, 128 live values)
// ============================================================================
__device__ __forceinline__ void ln_stats(float x, float* r1, float* r2,
                                         float& mu, float& rs) {
    float2 red = warpRed2(x, x * x);
    int wid = threadIdx.x >> 5, lane = threadIdx.x & 31;
    if (lane == 0) { r1[wid] = red.x; r2[wid] = red.y; }
    __syncthreads();
    float Sm = 0.f, Sq = 0.f;
    #pragma unroll
    for (int i = 0; i < 8; i++) { Sm += r1[i]; Sq += r2[i]; }
    mu = Sm * (1.0f / 128.0f);
    float var = Sq * (1.0f / 128.0f) - mu * mu;
    rs = rsqrtf(var + 1e-5f);
}

// ============================================================================
// Kernel 0: merged weight prep (blocks 0-127) + slot init / q proj (128-287)
// ============================================================================
__global__ void k_init2(const float* __restrict__ Wk, const float* __restrict__ Wv,
                        const float* __restrict__ noise, const float* __restrict__ smu,
                        const float* __restrict__ sls, const float* __restrict__ nsw,
                        const float* __restrict__ nsb, const float* __restrict__ Wq)
{
    __shared__ float sl[128];
    __shared__ float hm[128];
    __shared__ float hid[256];
    __shared__ float r1[8], r2[8];
    const int tid = threadIdx.x;

    if (blockIdx.x < 128) {
        int d = blockIdx.x, c = tid;
        g_wkT[d * C_ + c] = __float2bfloat16(Wk[c * D_ + d]);
        g_wvT[d * C_ + c] = __float2bfloat16(Wv[c * D_ + d]);
        return;
    }
    const int bs = blockIdx.x - 128;       // 0..159
    const int b = bs / 10;
    const int s = bs % 10;

    if (tid < 128) {
        float v = smu[tid] + expf(sls[tid]) * noise[bs * 128 + tid];
        g_slots[bs * 128 + tid] = v;
        sl[tid] = v;
        if (s < 6)
            g_qb[b * 2048 + (10 + s) * 128 + tid] = __float2bfloat16(0.f);
    }
    __syncthreads();

    float x = (tid < 128) ? sl[tid] : 0.f;
    float mu, rs;
    ln_stats(x, r1, r2, mu, rs);
    if (tid < 128) hm[tid] = (x - mu) * rs * nsw[tid] + nsb[tid];
    __syncthreads();
    {
        int d = tid & 127, half = tid >> 7;
        const float* wq = Wq + half * 64 * 128;
        const float* hh = hm + half * 64;
        float a0 = 0, a1 = 0, a2 = 0, a3 = 0;
        #pragma unroll
        for (int c = 0; c < 64; c += 4) {
            a0 += hh[c + 0] * wq[(c + 0) * 128 + d];
            a1 += hh[c + 1] * wq[(c + 1) * 128 + d];
            a2 += hh[c + 2] * wq[(c + 2) * 128 + d];
            a3 += hh[c + 3] * wq[(c + 3) * 128 + d];
        }
        hid[tid] = (a0 + a1) + (a2 + a3);
    }
    __syncthreads();
    if (tid < 128)
        g_qb[b * 2048 + s * 128 + tid] =
            __float2bfloat16((hid[tid] + hid[tid + 128]) * QSCALE);
}

// ============================================================================
// Kernel 1: fused LayerNorm + K,V projection, WARP-SPECIALIZED (proven).
// ============================================================================
#define XSTRIDE 264
#define SMEM1 (3 * 128 * XSTRIDE * 2)
__global__ __launch_bounds__(512, 1) void k_ln_kv(
    const float* __restrict__ obs, const float* __restrict__ niw,
    const float* __restrict__ nib)
{
    extern __shared__ char smx[];
    __nv_bfloat16* ha0 = (__nv_bfloat16*)smx;           // [64][264]
    __nv_bfloat16* ha1 = ha0 + 64 * XSTRIDE;
    __nv_bfloat16* wks = ha1 + 64 * XSTRIDE;            // [128][264]
    __nv_bfloat16* wvs = wks + 128 * XSTRIDE;

    const int tid  = threadIdx.x;
    const int wid  = tid >> 5;
    const int lane = tid & 31;
    const int tblk = blockIdx.x * 512;

    {
        const uint4* gk4 = (const uint4*)g_wkT;
        const uint4* gv4 = (const uint4*)g_wvT;
        #pragma unroll
        for (int i = 0; i < 8; i++) {
            int u = tid + i * 512;
            int row = u >> 5, c = u & 31;
            *(uint4*)((char*)wks + row * (XSTRIDE * 2) + c * 16) = gk4[u];
            *(uint4*)((char*)wvs + row * (XSTRIDE * 2) + c * 16) = gv4[u];
        }
    }

    if (wid >= 8) {
        // ================= PRODUCER: LayerNorm =================
        const int p  = wid - 8;
        const int c0 = lane * 4;
        float4 nw0 = *(const float4*)(niw + c0);
        float4 nw1 = *(const float4*)(niw + c0 + 128);
        float4 nb0 = *(const float4*)(nib + c0);
        float4 nb1 = *(const float4*)(nib + c0 + 128);

        #pragma unroll 1
        for (int h = -1; h < 8; h++) {
            if (h < 7) {
                const int hh = h + 1;
                __nv_bfloat16* buf = (hh & 1) ? ha1 : ha0;
                const int t0 = tblk + hh * 64;
                #pragma unroll
                for (int i = 0; i < 8; i++) {
                    int r = p * 8 + i;
                    const float4* src = (const float4*)(obs + (size_t)(t0 + r) * C_);
                    float4 v0 = __ldcs(src + lane);
                    float4 v1 = __ldcs(src + lane + 32);
                    float s  = v0.x + v0.y + v0.z + v0.w + v1.x + v1.y + v1.z + v1.w;
                    float ss = v0.x*v0.x + v0.y*v0.y + v0.z*v0.z + v0.w*v0.w
                             + v1.x*v1.x + v1.y*v1.y + v1.z*v1.z + v1.w*v1.w;
                    float2 red = warpRed2(s, ss);
                    float mu  = red.x * (1.0f / 256.0f);
                    float var = red.y * (1.0f / 256.0f) - mu * mu;
                    float rsg = rsqrtf(var + 1e-5f);
                    char* xr = (char*)buf + r * (XSTRIDE * 2);
                    *(__nv_bfloat162*)(xr + (c0 + 0) * 2) =
                        __floats2bfloat162_rn((v0.x - mu) * rsg * nw0.x + nb0.x,
                                              (v0.y - mu) * rsg * nw0.y + nb0.y);
                    *(__nv_bfloat162*)(xr + (c0 + 2) * 2) =
                        __floats2bfloat162_rn((v0.z - mu) * rsg * nw0.z + nb0.z,
                                              (v0.w - mu) * rsg * nw0.w + nb0.w);
                    *(__nv_bfloat162*)(xr + (c0 + 128) * 2) =
                        __floats2bfloat162_rn((v1.x - mu) * rsg * nw1.x + nb1.x,
                                              (v1.y - mu) * rsg * nw1.y + nb1.y);
                    *(__nv_bfloat162*)(xr + (c0 + 130) * 2) =
                        __floats2bfloat162_rn((v1.z - mu) * rsg * nw1.z + nb1.z,
                                              (v1.w - mu) * rsg * nw1.w + nb1.w);
                }
            }
            __syncthreads();
        }
    } else {
        // ================= CONSUMER: MMA + epilogue =================
        const int mat = wid >> 2;
        const int wm  = wid & 1;
        const int wn  = (wid >> 1) & 1;
        const __nv_bfloat16* wsm = mat ? wvs : wks;
        const int ga = lane >> 3, ra = lane & 7;
        const uint32_t aB0 = s2u(wsm) +
            (uint32_t)(((wn * 64 + ra + ((ga >> 1) << 3)) * XSTRIDE + ((ga & 1) << 3)) * 2);
        const uint32_t aAoff =
            (uint32_t)(((wm * 32 + ra + ((ga & 1) << 3)) * XSTRIDE + ((ga >> 1) << 3)) * 2);
        const int qrow = lane >> 2;
        const int qcol = (lane & 3) * 2;
        __nv_bfloat16* gout = mat ? g_v : g_k;

        __syncthreads();
        #pragma unroll 1
        for (int h = 0; h < 8; h++) {
            const __nv_bfloat16* abuf = (h & 1) ? ha1 : ha0;
            uint32_t aA = s2u(abuf) + aAoff;
            uint32_t aB = aB0;

            float acc[2][8][4];
            #pragma unroll
            for (int mi = 0; mi < 2; mi++)
                #pragma unroll
                for (int nj = 0; nj < 8; nj++)
                    #pragma unroll
                    for (int e = 0; e < 4; e++) acc[mi][nj][e] = 0.f;

            #pragma unroll 1
            for (int s = 0; s < 16; s++) {
                uint32_t A0[4], A1[4], Bx[4][4];
                LDSM4(A0, aA);
                LDSM4(A1, aA + 16 * (XSTRIDE * 2));
                #pragma unroll
                for (int j = 0; j < 4; j++)
                    LDSM4(Bx[j], aB + j * 16 * (XSTRIDE * 2));
                #pragma unroll
                for (int nj = 0; nj < 8; nj++) {
                    uint32_t b0 = Bx[nj >> 1][(nj & 1) * 2];
                    uint32_t b1 = Bx[nj >> 1][(nj & 1) * 2 + 1];
                    MMA_BF16(acc[0][nj], A0, b0, b1);
                    MMA_BF16(acc[1][nj], A1, b0, b1);
                }
                aA += 32;
                aB += 32;
            }

            const int rbase = tblk + h * 64 + wm * 32;
            #pragma unroll
            for (int mi = 0; mi < 2; mi++) {
                #pragma unroll
                for (int nj = 0; nj < 8; nj++) {
                    int c  = wn * 64 + nj * 8 + qcol;
                    int r0 = rbase + mi * 16 + qrow;
                    *(__nv_bfloat162*)(gout + (size_t)r0 * D_ + c) =
                        __floats2bfloat162_rn(acc[mi][nj][0], acc[mi][nj][1]);
                    *(__nv_bfloat162*)(gout + (size_t)(r0 + 8) * D_ + c) =
                        __floats2bfloat162_rn(acc[mi][nj][2], acc[mi][nj][3]);
                }
            }
            __syncthreads();
        }
    }
}

// ============================================================================
// Kernel 3: fused attention, 2 chunks/CTA, staggered cp.async, REGISTER
// accumulation of numerator + denominators across both chunks (one partial
// write per CTA -> NCH2=16 partials). grid (16,16), 256 thr, 2 CTAs/SM.
// ============================================================================
#define TS 136
#define LSTR 132
#define ATT_SMEM (2*128*TS*2 + 16*TS*2 + 16*TS*2 + 16*LSTR*4)
__global__ __launch_bounds__(256, 2) void k_attn()
{
    extern __shared__ char sm2[];
    __nv_bfloat16* tileK = (__nv_bfloat16*)sm2;
    __nv_bfloat16* tileV = tileK + 128 * TS;
    __nv_bfloat16* Qs    = tileV + 128 * TS;
    __nv_bfloat16* aBm   = Qs + 16 * TS;
    float* Ls            = (float*)(aBm + 16 * TS);

    const int tid  = threadIdx.x;
    const int w    = tid >> 5;
    const int lane = tid & 31;
    const int blk  = blockIdx.x;          // 0..15
    const int ck0  = blk * 2;
    const int b    = blockIdx.y;

    const uint32_t dK = s2u(tileK), dV = s2u(tileV);
    const uint4* srcK0 = (const uint4*)(g_k + ((size_t)b * NPB + ck0 * CHUNK) * D_);
    const uint4* srcV0 = (const uint4*)(g_v + ((size_t)b * NPB + ck0 * CHUNK) * D_);

    #pragma unroll
    for (int i = 0; i < 8; i++) {
        int u = tid + i * 256;
        int row = u >> 4, c = u & 15;
        CPASYNC16(dK + row * (TS * 2) + c * 16, srcK0 + u);
    }
    CPCOMMIT();
    #pragma unroll
    for (int i = 0; i < 8; i++) {
        int u = tid + i * 256;
        int row = u >> 4, c = u & 15;
        CPASYNC16(dV + row * (TS * 2) + c * 16, srcV0 + u);
    }
    CPCOMMIT();

    {
        int row = tid >> 4, c = tid & 15;
        *(uint4*)((char*)Qs + row * (TS * 2) + c * 16) =
            ((const uint4*)(g_qb + b * 2048))[tid];
    }
    if (tid < 102) {
        *(uint4*)((char*)aBm + 10 * (TS * 2) + tid * 16) = make_uint4(0, 0, 0, 0);
    }

    CPWAIT(1);      // K0 ready
    __syncthreads();

    const int ga = lane >> 3, ra = lane & 7;
    const int qrow = lane >> 2, qcol = (lane & 3) * 2;
    const uint32_t baseA_q = s2u(Qs) +
        (uint32_t)(((ra + ((ga & 1) << 3)) * TS + ((ga >> 1) << 3)) * 2);
    const uint32_t baseB_k = s2u(tileK) +
        (uint32_t)(((w * 16 + ra + ((ga >> 1) << 3)) * TS + ((ga & 1) << 3)) * 2);
    const uint32_t baseA_a = s2u(aBm) +
        (uint32_t)(((ra + ((ga & 1) << 3)) * TS + ((ga >> 1) << 3)) * 2);
    const uint32_t baseB_v = s2u(tileV) +
        (uint32_t)(((((ga & 1) << 3) + ra) * TS + w * 16 + ((ga >> 1) << 3)) * 2);

    float nacc[2][4] = {{0,0,0,0},{0,0,0,0}};   // accumulated across BOTH chunks
    float dacc[2] = {0.f, 0.f};                 // per-warp slot dens (s=w, s=w+8)

    #pragma unroll 1
    for (int cc = 0; cc < 2; cc++) {
        // ---- logits MMA ----
        {
            float lacc[2][4] = {{0,0,0,0},{0,0,0,0}};
            #pragma unroll
            for (int ks = 0; ks < 8; ks++) {
                uint32_t A[4], Bx[4];
                LDSM4(A, baseA_q + ks * 32);
                LDSM4(Bx, baseB_k + ks * 32);
                MMA_BF16(lacc[0], A, Bx[0], Bx[1]);
                MMA_BF16(lacc[1], A, Bx[2], Bx[3]);
            }
            #pragma unroll
            for (int nj = 0; nj < 2; nj++) {
                int t = w * 16 + nj * 8 + qcol;
                Ls[qrow * LSTR + t]           = lacc[nj][0];
                Ls[qrow * LSTR + t + 1]       = lacc[nj][1];
                Ls[(qrow + 8) * LSTR + t]     = lacc[nj][2];
                Ls[(qrow + 8) * LSTR + t + 1] = lacc[nj][3];
            }
        }
        __syncthreads();

        // ---- softmax over 10 slots ----
        if (tid < 128) {
            float v[10]; float m = -1e30f;
            #pragma unroll
            for (int s = 0; s < 10; s++) { v[s] = Ls[s * LSTR + tid]; m = fmaxf(m, v[s]); }
            float sum = 0.f;
            #pragma unroll
            for (int s = 0; s < 10; s++) { v[s] = __expf(v[s] - m); sum += v[s]; }
            float inv = 1.0f / sum;
            #pragma unroll
            for (int s = 0; s < 10; s++) aBm[s * TS + tid] = __float2bfloat16(v[s] * inv);
        }
        __syncthreads();

        // ---- chunk 0 only: tileK dead -> prefetch K1 ----
        if (cc == 0) {
            const uint4* srcK1 =
                (const uint4*)(g_k + ((size_t)b * NPB + (ck0 + 1) * CHUNK) * D_);
            #pragma unroll
            for (int i = 0; i < 8; i++) {
                int u = tid + i * 256;
                int row = u >> 4, c = u & 15;
                CPASYNC16(dK + row * (TS * 2) + c * 16, srcK1 + u);
            }
            CPCOMMIT();
        }

        // ---- denominators: accumulate into registers ----
        {
            int idx = 0;
            for (int s = w; s < 10; s += 8) {
                float p = bf(aBm[s * TS + lane]) + bf(aBm[s * TS + lane + 32])
                        + bf(aBm[s * TS + lane + 64]) + bf(aBm[s * TS + lane + 96]);
                p = warpRed1(p);
                dacc[idx] += p;
                idx++;
            }
        }

        if (cc == 0) { CPWAIT(1); } else { CPWAIT(0); }
        __syncthreads();

        // ---- numerator MMA: accumulate across chunks ----
        {
            #pragma unroll
            for (int ks = 0; ks < 8; ks++) {
                uint32_t A[4], Bt[4];
                LDSM4(A, baseA_a + ks * 32);
                LDSM4T(Bt, baseB_v + ks * (16 * TS * 2));
                MMA_BF16(nacc[0], A, Bt[0], Bt[1]);
                MMA_BF16(nacc[1], A, Bt[2], Bt[3]);
            }
        }

        if (cc == 0) {
            __syncthreads();     // all warps done reading tileV
            const uint4* srcV1 =
                (const uint4*)(g_v + ((size_t)b * NPB + (ck0 + 1) * CHUNK) * D_);
            #pragma unroll
            for (int i = 0; i < 8; i++) {
                int u = tid + i * 256;
                int row = u >> 4, c = u & 15;
                CPASYNC16(dV + row * (TS * 2) + c * 16, srcV1 + u);
            }
            CPCOMMIT();
            CPWAIT(1);           // K1 done
            __syncthreads();
        }
    }

    // ---- single partial write per CTA ----
    {
        float* dst = g_pnum + (size_t)(b * NCH2 + blk) * S_ * D_;
        #pragma unroll
        for (int nj = 0; nj < 2; nj++) {
            int d = w * 16 + nj * 8 + qcol;
            *(float2*)(dst + qrow * D_ + d) = make_float2(nacc[nj][0], nacc[nj][1]);
            if (qrow + 8 < 10)
                *(float2*)(dst + (qrow + 8) * D_ + d) =
                    make_float2(nacc[nj][2], nacc[nj][3]);
        }
        int idx = 0;
        for (int s = w; s < 10; s += 8) {
            if (lane == 0) g_pden[(b * NCH2 + blk) * S_ + s] = dacc[idx];
            idx++;
        }
    }
}

// ============================================================================
// Kernel 4: slot update + q projection.  grid 160, 256 thr. (16 partials)
// ============================================================================
__global__ void k_slotq(const float* __restrict__ nmw, const float* __restrict__ nmb,
                        const float* __restrict__ w1, const float* __restrict__ b1,
                        const float* __restrict__ w2, const float* __restrict__ b2,
                        const float* __restrict__ nsw, const float* __restrict__ nsb,
                        const float* __restrict__ Wq)
{
    __shared__ float sl[128];
    __shared__ float hm[128];
    __shared__ float hid[256];
    __shared__ float r1[8], r2[8];
    __shared__ float sden;
    const int tid = threadIdx.x;
    const int b = blockIdx.x / 10;
    const int s = blockIdx.x % 10;

    if ((tid >> 5) == 4) {
        int lane = tid & 31;
        float p = (lane < NCH2) ? g_pden[(b * NCH2 + lane) * S_ + s] : 0.f;
        p = warpRed1(p);
        if (lane == 0) sden = p;
    }
    float u0 = 0, u1 = 0, u2 = 0, u3 = 0;
    if (tid < 128) {
        const float* src = g_pnum + ((size_t)(b * NCH2) * S_ + s) * D_ + tid;
        #pragma unroll
        for (int ch = 0; ch < NCH2; ch += 4) {
            u0 += __ldcs(src + (size_t)(ch + 0) * S_ * D_);
            u1 += __ldcs(src + (size_t)(ch + 1) * S_ * D_);
            u2 += __ldcs(src + (size_t)(ch + 2) * S_ * D_);
            u3 += __ldcs(src + (size_t)(ch + 3) * S_ * D_);
        }
    }
    __syncthreads();
    float slot_new = 0.f;
    if (tid < 128)
        slot_new = g_slots[(b * S_ + s) * D_ + tid]
                 + ((u0 + u1) + (u2 + u3)) / (sden + 1e-8f);
    float mu, rs;
    ln_stats(tid < 128 ? slot_new : 0.f, r1, r2, mu, rs);
    if (tid < 128) hm[tid] = (slot_new - mu) * rs * nmw[tid] + nmb[tid];
    __syncthreads();
    {
        float a0 = 0, a1 = 0, a2 = 0, a3 = 0;
        #pragma unroll
        for (int c = 0; c < 128; c += 4) {
            a0 += hm[c + 0] * w1[(c + 0) * 256 + tid];
            a1 += hm[c + 1] * w1[(c + 1) * 256 + tid];
            a2 += hm[c + 2] * w1[(c + 2) * 256 + tid];
            a3 += hm[c + 3] * w1[(c + 3) * 256 + tid];
        }
        hid[tid] = fmaxf(b1[tid] + (a0 + a1) + (a2 + a3), 0.f);
    }
    __syncthreads();
    if (tid < 128) {
        float o0 = 0, o1 = 0, o2 = 0, o3 = 0;
        #pragma unroll 16
        for (int j = 0; j < 256; j += 4) {
            o0 += hid[j + 0] * w2[(j + 0) * 128 + tid];
            o1 += hid[j + 1] * w2[(j + 1) * 128 + tid];
            o2 += hid[j + 2] * w2[(j + 2) * 128 + tid];
            o3 += hid[j + 3] * w2[(j + 3) * 128 + tid];
        }
        float sf = slot_new + b2[tid] + (o0 + o1) + (o2 + o3);
        sl[tid] = sf;
        g_slots[(b * S_ + s) * D_ + tid] = sf;
    }
    __syncthreads();

    float x = (tid < 128) ? sl[tid] : 0.f;
    ln_stats(x, r1, r2, mu, rs);
    if (tid < 128) hm[tid] = (x - mu) * rs * nsw[tid] + nsb[tid];
    __syncthreads();
    {
        int d = tid & 127, half = tid >> 7;
        const float* wq = Wq + half * 64 * 128;
        const float* hh = hm + half * 64;
        float a0 = 0, a1 = 0, a2 = 0, a3 = 0;
        #pragma unroll
        for (int c = 0; c < 64; c += 4) {
            a0 += hh[c + 0] * wq[(c + 0) * 128 + d];
            a1 += hh[c + 1] * wq[(c + 1) * 128 + d];
            a2 += hh[c + 2] * wq[(c + 2) * 128 + d];
            a3 += hh[c + 3] * wq[(c + 3) * 128 + d];
        }
        hid[tid] = (a0 + a1) + (a2 + a3);
    }
    __syncthreads();
    if (tid < 128)
        g_qb[b * 2048 + s * 128 + tid] =
            __float2bfloat16((hid[tid] + hid[tid + 128]) * QSCALE);
}

// ============================================================================
// Kernel 5: final update + heads.  grid 160, 256 thr. (16 partials)
// ============================================================================
__global__ void k_last(const float* __restrict__ nmw, const float* __restrict__ nmb,
                       const float* __restrict__ w1, const float* __restrict__ b1,
                       const float* __restrict__ w2, const float* __restrict__ b2,
                       const float* __restrict__ pw1, const float* __restrict__ pb1,
                       const float* __restrict__ pw2, const float* __restrict__ pb2,
                       const float* __restrict__ tw, const float* __restrict__ tb,
                       float* __restrict__ out)
{
    __shared__ float sl[128];
    __shared__ float hm[128];
    __shared__ float hid[256];
    __shared__ float r1[8], r2[8];
    __shared__ float sden;
    const int tid = threadIdx.x;
    const int b = blockIdx.x / 10;
    const int s = blockIdx.x % 10;

    if ((tid >> 5) == 4) {
        int lane = tid & 31;
        float p = (lane < NCH2) ? g_pden[(b * NCH2 + lane) * S_ + s] : 0.f;
        p = warpRed1(p);
        if (lane == 0) sden = p;
    }
    float u0 = 0, u1 = 0, u2 = 0, u3 = 0;
    if (tid < 128) {
        const float* src = g_pnum + ((size_t)(b * NCH2) * S_ + s) * D_ + tid;
        #pragma unroll
        for (int ch = 0; ch < NCH2; ch += 4) {
            u0 += __ldcs(src + (size_t)(ch + 0) * S_ * D_);
            u1 += __ldcs(src + (size_t)(ch + 1) * S_ * D_);
            u2 += __ldcs(src + (size_t)(ch + 2) * S_ * D_);
            u3 += __ldcs(src + (size_t)(ch + 3) * S_ * D_);
        }
    }
    __syncthreads();
    float slot_new = 0.f;
    if (tid < 128)
        slot_new = g_slots[(b * S_ + s) * D_ + tid]
                 + ((u0 + u1) + (u2 + u3)) / (sden + 1e-8f);
    float mu, rs;
    ln_stats(tid < 128 ? slot_new : 0.f, r1, r2, mu, rs);
    if (tid < 128) hm[tid] = (slot_new - mu) * rs * nmw[tid] + nmb[tid];
    __syncthreads();
    {
        float a0 = 0, a1 = 0, a2 = 0, a3 = 0;
        #pragma unroll
        for (int c = 0; c < 128; c += 4) {
            a0 += hm[c + 0] * w1[(c + 0) * 256 + tid];
            a1 += hm[c + 1] * w1[(c + 1) * 256 + tid];
            a2 += hm[c + 2] * w1[(c + 2) * 256 + tid];
            a3 += hm[c + 3] * w1[(c + 3) * 256 + tid];
        }
        hid[tid] = fmaxf(b1[tid] + (a0 + a1) + (a2 + a3), 0.f);
    }
    __syncthreads();
    if (tid < 128) {
        float o0 = 0, o1 = 0, o2 = 0, o3 = 0;
        #pragma unroll 16
        for (int j = 0; j < 256; j += 4) {
            o0 += hid[j + 0] * w2[(j + 0) * 128 + tid];
            o1 += hid[j + 1] * w2[(j + 1) * 128 + tid];
            o2 += hid[j + 2] * w2[(j + 2) * 128 + tid];
            o3 += hid[j + 3] * w2[(j + 3) * 128 + tid];
        }
        sl[tid] = slot_new + b2[tid] + (o0 + o1) + (o2 + o3);
    }
    __syncthreads();

    {
        float a0 = 0, a1 = 0, a2 = 0, a3 = 0;
        #pragma unroll
        for (int c = 0; c < 128; c += 4) {
            a0 += sl[c + 0] * pw1[(c + 0) * 256 + tid];
            a1 += sl[c + 1] * pw1[(c + 1) * 256 + tid];
            a2 += sl[c + 2] * pw1[(c + 2) * 256 + tid];
            a3 += sl[c + 3] * pw1[(c + 3) * 256 + tid];
        }
        hid[tid] = fmaxf(pb1[tid] + (a0 + a1) + (a2 + a3), 0.f);
    }
    __syncthreads();
    if (tid < 128) {
        float o0 = 0, o1 = 0, o2 = 0, o3 = 0;
        #pragma unroll 16
        for (int j = 0; j < 256; j += 4) {
            o0 += hid[j + 0] * pw2[(j + 0) * 128 + tid];
            o1 += hid[j + 1] * pw2[(j + 1) * 128 + tid];
            o2 += hid[j + 2] * pw2[(j + 2) * 128 + tid];
            o3 += hid[j + 3] * pw2[(j + 3) * 128 + tid];
        }
        out[blockIdx.x * 128 + tid] = pb2[tid] + (o0 + o1) + (o2 + o3);
    } else if (tid < 128 + T_) {
        int tt = tid - 128;
        float o = tb[tt];
        #pragma unroll 4
        for (int c = 0; c < 128; c++) o += sl[c] * tw[c * T_ + tt];
        out[B_ * S_ * D_ + blockIdx.x * T_ + tt] = o;
    }
}

// ============================================================================
extern "C" void kernel_launch(void* const* d_in, const int* in_sizes, int n_in,
                              void* d_out, int out_size)
{
    const float* obs  = (const float*)d_in[0];
    const float* noise= (const float*)d_in[1];
    const float* smu  = (const float*)d_in[2];
    const float* sls  = (const float*)d_in[3];
    const float* niw  = (const float*)d_in[4];
    const float* nib  = (const float*)d_in[5];
    const float* nsw  = (const float*)d_in[6];
    const float* nsb  = (const float*)d_in[7];
    const float* nmw  = (const float*)d_in[8];
    const float* nmb  = (const float*)d_in[9];
    const float* Wq   = (const float*)d_in[10];
    const float* Wk   = (const float*)d_in[11];
    const float* Wv   = (const float*)d_in[12];
    const float* mw1  = (const float*)d_in[13];
    const float* mb1  = (const float*)d_in[14];
    const float* mw2  = (const float*)d_in[15];
    const float* mb2  = (const float*)d_in[16];
    const float* pw1  = (const float*)d_in[17];
    const float* pb1  = (const float*)d_in[18];
    const float* pw2  = (const float*)d_in[19];
    const float* pb2  = (const float*)d_in[20];
    const float* tcw  = (const float*)d_in[21];
    const float* tcb  = (const float*)d_in[22];
    float* out = (float*)d_out;

    cudaFuncSetAttribute(k_ln_kv, cudaFuncAttributeMaxDynamicSharedMemorySize, SMEM1);
    cudaFuncSetAttribute(k_attn,  cudaFuncAttributeMaxDynamicSharedMemorySize, ATT_SMEM);

    k_init2<<<288, 256>>>(Wk, Wv, noise, smu, sls, nsw, nsb, Wq);        // 1
    k_ln_kv<<<NTOK / 512, 512, SMEM1>>>(obs, niw, nib);                  // 2
    dim3 g2(NCHUNK / 2, B_);
    for (int it = 0; it < 3; it++) {
        k_attn<<<g2, 256, ATT_SMEM>>>();                                 // 3
        if (it < 2)
            k_slotq<<<160, 256>>>(nmw, nmb, mw1, mb1, mw2, mb2, nsw, nsb, Wq);  // 4 <- ncu
        else
            k_last<<<160, 256>>>(nmw, nmb, mw1, mb1, mw2, mb2,
                                 pw1, pb1, pw2, pb2, tcw, tcb, out);
    }
}